// round 1
// baseline (speedup 1.0000x reference)
#include <cuda_runtime.h>

// Problem constants
#define BB 4
#define SS 1024
#define HH 16
#define DD 64
#define DMM 1024

static const int M_ROWS = BB * SS;          // 4096
static const size_t OUT_ELEMS = (size_t)BB * SS * DMM;          // 4194304
static const size_t ATT_ELEMS = (size_t)BB * HH * SS * SS;      // 67108864

// Scratch (allocation-free rule: __device__ globals)
__device__ float g_Q[BB * HH * SS * DD];
__device__ float g_K[BB * HH * SS * DD];
__device__ float g_V[BB * HH * SS * DD];
__device__ float g_ctx[BB * SS * DMM];
__device__ float g_attn[(size_t)BB * HH * SS * SS];  // fallback if d_out lacks attn region

// ----------------------------------------------------------------------------
// C[m][n] = scale * sum_k A[m*lda+k] * B[n*ldb+k]   (both K-contiguous, "NT")
// 128x128 tile, BK=16, 256 threads, 8x8 per thread.
// mode 0: row-major C (ldc). mode 1: scatter to (B,H,S,D) from m=(b,s), n=(h,d).
// ----------------------------------------------------------------------------
__global__ void __launch_bounds__(256) gemm_nt(
    const float* __restrict__ A, const float* __restrict__ B, float* __restrict__ C,
    int K, int lda, int ldb, int ldc,
    long strideAz, long strideBz, long strideCz,
    float scale, int mode)
{
    __shared__ float As[16][132];
    __shared__ float Bs[16][132];
    const int tid = threadIdx.x;
    const int tx = tid & 15, ty = tid >> 4;
    const int m0 = blockIdx.y * 128, n0 = blockIdx.x * 128;
    A += (long)blockIdx.z * strideAz;
    B += (long)blockIdx.z * strideBz;
    C += (long)blockIdx.z * strideCz;

    float acc[8][8];
#pragma unroll
    for (int i = 0; i < 8; ++i)
#pragma unroll
        for (int j = 0; j < 8; ++j) acc[i][j] = 0.f;

    for (int k0 = 0; k0 < K; k0 += 16) {
#pragma unroll
        for (int t = 0; t < 2; ++t) {
            int idx = tid + t * 256;            // 0..511
            int row = idx >> 2;
            int c4  = (idx & 3) << 2;
            float4 va = *(const float4*)(A + (long)(m0 + row) * lda + k0 + c4);
            As[c4 + 0][row] = va.x; As[c4 + 1][row] = va.y;
            As[c4 + 2][row] = va.z; As[c4 + 3][row] = va.w;
            float4 vb = *(const float4*)(B + (long)(n0 + row) * ldb + k0 + c4);
            Bs[c4 + 0][row] = vb.x; Bs[c4 + 1][row] = vb.y;
            Bs[c4 + 2][row] = vb.z; Bs[c4 + 3][row] = vb.w;
        }
        __syncthreads();
#pragma unroll
        for (int kk = 0; kk < 16; ++kk) {
            float a[8], b[8];
            *(float4*)(a)     = *(const float4*)&As[kk][ty * 8];
            *(float4*)(a + 4) = *(const float4*)&As[kk][ty * 8 + 4];
            *(float4*)(b)     = *(const float4*)&Bs[kk][tx * 8];
            *(float4*)(b + 4) = *(const float4*)&Bs[kk][tx * 8 + 4];
#pragma unroll
            for (int i = 0; i < 8; ++i)
#pragma unroll
                for (int j = 0; j < 8; ++j) acc[i][j] += a[i] * b[j];
        }
        __syncthreads();
    }

    if (mode == 0) {
#pragma unroll
        for (int i = 0; i < 8; ++i) {
            int m = m0 + ty * 8 + i;
            float4 o0 = make_float4(acc[i][0] * scale, acc[i][1] * scale,
                                    acc[i][2] * scale, acc[i][3] * scale);
            float4 o1 = make_float4(acc[i][4] * scale, acc[i][5] * scale,
                                    acc[i][6] * scale, acc[i][7] * scale);
            *(float4*)(C + (long)m * ldc + n0 + tx * 8)     = o0;
            *(float4*)(C + (long)m * ldc + n0 + tx * 8 + 4) = o1;
        }
    } else {
        int n = n0 + tx * 8;
        int h = n >> 6, dbase = n & 63;       // 8-wide aligned, never crosses 64
#pragma unroll
        for (int i = 0; i < 8; ++i) {
            int m = m0 + ty * 8 + i;
            int b = m >> 10, s = m & 1023;
            float* dst = C + (((long)(b * HH + h) * SS + s) * DD + dbase);
            *(float4*)(dst)     = make_float4(acc[i][0], acc[i][1], acc[i][2], acc[i][3]);
            *(float4*)(dst + 4) = make_float4(acc[i][4], acc[i][5], acc[i][6], acc[i][7]);
        }
    }
}

// ----------------------------------------------------------------------------
// ctx = attn @ V per (b,h):  M=1024 (q), N=64 (d), K=1024 (k). 128x64 tile, BK=32.
// Scatters result to (B,S,DM).
// ----------------------------------------------------------------------------
__global__ void __launch_bounds__(256) gemm_nn_ctx(
    const float* __restrict__ attn, const float* __restrict__ V, float* __restrict__ ctx)
{
    __shared__ float As[32][132];
    __shared__ float Bs[32][68];
    const int z = blockIdx.z;                 // bh
    const float* A  = attn + (long)z * SS * SS;
    const float* Bv = V    + (long)z * SS * DD;
    const int b = z >> 4, h = z & 15;
    const int m0 = blockIdx.y * 128;
    const int tid = threadIdx.x;
    const int tx = tid & 15, ty = tid >> 4;   // tx: 4 cols, ty: 8 rows

    float acc[8][4];
#pragma unroll
    for (int i = 0; i < 8; ++i)
#pragma unroll
        for (int j = 0; j < 4; ++j) acc[i][j] = 0.f;

    for (int k0 = 0; k0 < SS; k0 += 32) {
#pragma unroll
        for (int t = 0; t < 4; ++t) {
            int idx = tid + t * 256;          // 0..1023 over 128x32 A tile
            int row = idx >> 3;
            int c4  = (idx & 7) << 2;
            float4 va = *(const float4*)(A + (long)(m0 + row) * SS + k0 + c4);
            As[c4 + 0][row] = va.x; As[c4 + 1][row] = va.y;
            As[c4 + 2][row] = va.z; As[c4 + 3][row] = va.w;
        }
#pragma unroll
        for (int t = 0; t < 2; ++t) {
            int idx = tid + t * 256;          // 0..511 over 32x64 B tile
            int row = idx >> 4;
            int c4  = (idx & 15) << 2;
            *(float4*)&Bs[row][c4] = *(const float4*)(Bv + (long)(k0 + row) * DD + c4);
        }
        __syncthreads();
#pragma unroll
        for (int kk = 0; kk < 32; ++kk) {
            float a[8], bb[4];
            *(float4*)(a)     = *(const float4*)&As[kk][ty * 8];
            *(float4*)(a + 4) = *(const float4*)&As[kk][ty * 8 + 4];
            *(float4*)(bb)    = *(const float4*)&Bs[kk][tx * 4];
#pragma unroll
            for (int i = 0; i < 8; ++i)
#pragma unroll
                for (int j = 0; j < 4; ++j) acc[i][j] += a[i] * bb[j];
        }
        __syncthreads();
    }

#pragma unroll
    for (int i = 0; i < 8; ++i) {
        int q = m0 + ty * 8 + i;
        float* dst = ctx + ((long)(b * SS + q)) * DMM + h * DD + tx * 4;
        *(float4*)dst = make_float4(acc[i][0], acc[i][1], acc[i][2], acc[i][3]);
    }
}

// ----------------------------------------------------------------------------
// Row softmax in place: one block per row of 1024.
// ----------------------------------------------------------------------------
__global__ void __launch_bounds__(256) softmax_rows(float* __restrict__ attn)
{
    const long row = blockIdx.x;
    float* p = attn + row * 1024;
    const int tid = threadIdx.x;
    float4 v = ((float4*)p)[tid];

    float m = fmaxf(fmaxf(v.x, v.y), fmaxf(v.z, v.w));
#pragma unroll
    for (int o = 16; o; o >>= 1) m = fmaxf(m, __shfl_xor_sync(0xffffffffu, m, o));

    __shared__ float sm[8];
    __shared__ float ssum[8];
    const int wid = tid >> 5, lid = tid & 31;
    if (lid == 0) sm[wid] = m;
    __syncthreads();
    float bm = sm[0];
#pragma unroll
    for (int i = 1; i < 8; ++i) bm = fmaxf(bm, sm[i]);

    float e0 = __expf(v.x - bm), e1 = __expf(v.y - bm);
    float e2 = __expf(v.z - bm), e3 = __expf(v.w - bm);
    float s = e0 + e1 + e2 + e3;
#pragma unroll
    for (int o = 16; o; o >>= 1) s += __shfl_xor_sync(0xffffffffu, s, o);
    if (lid == 0) ssum[wid] = s;
    __syncthreads();
    float bs = 0.f;
#pragma unroll
    for (int i = 0; i < 8; ++i) bs += ssum[i];

    float inv = 1.0f / bs;
    ((float4*)p)[tid] = make_float4(e0 * inv, e1 * inv, e2 * inv, e3 * inv);
}

// ----------------------------------------------------------------------------
extern "C" void kernel_launch(void* const* d_in, const int* in_sizes, int n_in,
                              void* d_out, int out_size)
{
    const float* query = (const float*)d_in[0];
    const float* key   = (const float*)d_in[1];
    const float* value = (const float*)d_in[2];
    const float* Wq    = (const float*)d_in[3];
    const float* Wk    = (const float*)d_in[4];
    const float* Wv    = (const float*)d_in[5];
    const float* Wo    = (const float*)d_in[6];
    float* out = (float*)d_out;

    float *Qp, *Kp, *Vp, *Cp, *Ap;
    cudaGetSymbolAddress((void**)&Qp, g_Q);
    cudaGetSymbolAddress((void**)&Kp, g_K);
    cudaGetSymbolAddress((void**)&Vp, g_V);
    cudaGetSymbolAddress((void**)&Cp, g_ctx);
    cudaGetSymbolAddress((void**)&Ap, g_attn);

    // attn lives in d_out (after `out`) if the harness expects both tuple outputs.
    float* attn = ((size_t)out_size >= OUT_ELEMS + ATT_ELEMS) ? (out + OUT_ELEMS) : Ap;

    dim3 blk(256);

    // Q/K/V projections: X @ W^T scattered to (B,H,S,D)
    gemm_nt<<<dim3(8, 32, 1), blk>>>(query, Wq, Qp, DMM, DMM, DMM, 0, 0, 0, 0, 1.0f, 1);
    gemm_nt<<<dim3(8, 32, 1), blk>>>(key,   Wk, Kp, DMM, DMM, DMM, 0, 0, 0, 0, 1.0f, 1);
    gemm_nt<<<dim3(8, 32, 1), blk>>>(value, Wv, Vp, DMM, DMM, DMM, 0, 0, 0, 0, 1.0f, 1);

    // scores = Q K^T / 8, batched over 64 (b,h)
    gemm_nt<<<dim3(8, 8, BB * HH), blk>>>(Qp, Kp, attn, DD, DD, DD, SS,
                                          (long)SS * DD, (long)SS * DD, (long)SS * SS,
                                          0.125f, 0);

    // softmax in place over last dim
    softmax_rows<<<BB * HH * SS, 256>>>(attn);

    // ctx = attn @ V, scattered back to (B,S,DM)
    gemm_nn_ctx<<<dim3(1, 8, BB * HH), blk>>>(attn, Vp, Cp);

    // out = ctx @ Wo^T
    gemm_nt<<<dim3(8, 32, 1), blk>>>(Cp, Wo, out, DMM, DMM, DMM, DMM, 0, 0, 0, 1.0f, 0);
}

// round 3
// speedup vs baseline: 1.8383x; 1.8383x over previous
#include <cuda_runtime.h>
#include <cuda_bf16.h>
#include <cstdint>

#define BB 4
#define SS 1024
#define HH 16
#define DD 64
#define DMM 1024

static const size_t OUT_ELEMS = (size_t)BB * SS * DMM;        // 4194304
static const size_t ATT_ELEMS = (size_t)BB * HH * SS * SS;    // 67108864

// Scratch (__device__ globals: allocation-free rule)
__device__ float g_Q[BB * HH * SS * DD];
__device__ float g_K[BB * HH * SS * DD];
__device__ float g_Vt[BB * HH * DD * SS];   // V transposed: [bh][d][s]
__device__ float g_ctx[BB * SS * DMM];
__device__ float g_attn[(size_t)BB * HH * SS * SS];

// ---------------------------------------------------------------------------
__device__ __forceinline__ uint32_t smem_u32(const void* p) {
    uint32_t a;
    asm("{ .reg .u64 t; cvta.to.shared.u64 t, %1; cvt.u32.u64 %0, t; }" : "=r"(a) : "l"(p));
    return a;
}

__device__ __forceinline__ void ldsm4(uint32_t* r, uint32_t addr) {
    asm volatile("ldmatrix.sync.aligned.m8n8.x4.shared.b16 {%0,%1,%2,%3}, [%4];"
        : "=r"(r[0]), "=r"(r[1]), "=r"(r[2]), "=r"(r[3]) : "r"(addr));
}
__device__ __forceinline__ void ldsm2(uint32_t* r, uint32_t addr) {
    asm volatile("ldmatrix.sync.aligned.m8n8.x2.shared.b16 {%0,%1}, [%2];"
        : "=r"(r[0]), "=r"(r[1]) : "r"(addr));
}
__device__ __forceinline__ void mma16816(float* d, const uint32_t* a, const uint32_t* b) {
    asm volatile("mma.sync.aligned.m16n8k16.row.col.f32.bf16.bf16.f32 "
        "{%0,%1,%2,%3}, {%4,%5,%6,%7}, {%8,%9}, {%0,%1,%2,%3};"
        : "+f"(d[0]), "+f"(d[1]), "+f"(d[2]), "+f"(d[3])
        : "r"(a[0]), "r"(a[1]), "r"(a[2]), "r"(a[3]), "r"(b[0]), "r"(b[1]));
}
#define STS64(addr, r0, r1) \
    asm volatile("st.shared.v2.b32 [%0], {%1,%2};" :: "r"(addr), "r"(r0), "r"(r1) : "memory")

__device__ __forceinline__ void cvt_pair(float x, float y, uint32_t& hi, uint32_t& lo) {
    __nv_bfloat16 hx = __float2bfloat16(x), hy = __float2bfloat16(y);
    float rx = x - __bfloat162float(hx), ry = y - __bfloat162float(hy);
    __nv_bfloat16 lx = __float2bfloat16(rx), ly = __float2bfloat16(ry);
    hi = ((uint32_t)__bfloat16_as_ushort(hy) << 16) | __bfloat16_as_ushort(hx);
    lo = ((uint32_t)__bfloat16_as_ushort(ly) << 16) | __bfloat16_as_ushort(lx);
}

// ---------------------------------------------------------------------------
// Split-precision bf16 HMMA GEMM:  C[m][n] = sum_k A[m][k]*B[n][k]  (NT form)
// Block tile 128 x NT, BK=32 fp32 per chunk, 8 warps (2M x 4N), double-buffered
// smem (hi/lo parts), ldmatrix fragments, fp32 register accumulators.
// MODE: 0 = row-major C (ldc, sCz); 1 = scatter [bh][s][d]; 2 = scatter V^T
//       [bh][d][s]; 3 = scatter ctx [b,s,dm] (z=bh, n=d)
// ---------------------------------------------------------------------------
template<int NT, int MODE>
__global__ void __launch_bounds__(256) gemm_mma(
    const float* __restrict__ A, const float* __restrict__ B, float* __restrict__ C,
    int K, int lda, int ldb, int ldc,
    long sAz, long sBz, long sCz, float ascale)
{
    extern __shared__ char smem[];
    constexpr int WN  = NT / 4;        // warp N extent
    constexpr int NTC = WN / 8;        // n-tiles per warp
    constexpr int RB  = 80;            // padded row bytes (40 bf16)
    constexpr int ASZ = 128 * RB;      // one part (hi or lo) of A tile
    constexpr int BSZ = NT * RB;
    constexpr int STG = 2 * ASZ + 2 * BSZ;
    constexpr int BT4 = NT / 32;       // B float4 loads per thread

    const uint32_t sb = smem_u32(smem);
    const int tid = threadIdx.x, lane = tid & 31, wid = tid >> 5;
    const int wm = (wid & 1) * 64, wn = (wid >> 1) * WN;
    const int m0 = blockIdx.y * 128, n0 = blockIdx.x * NT;

    A += (long)blockIdx.z * sAz + (long)m0 * lda;
    B += (long)blockIdx.z * sBz + (long)n0 * ldb;

    float acc[4][NTC][4];
#pragma unroll
    for (int mt = 0; mt < 4; ++mt)
#pragma unroll
        for (int nt = 0; nt < NTC; ++nt)
#pragma unroll
            for (int j = 0; j < 4; ++j) acc[mt][nt][j] = 0.f;

    const int arow = tid >> 3;               // 0..31
    const int ac4  = (tid & 7) * 4;          // 0..28

    float4 ra[4], rb[BT4];

    auto LOADA = [&](int i) {
#pragma unroll
        for (int t = 0; t < 4; ++t)
            ra[t] = *(const float4*)(A + (long)(arow + t * 32) * lda + i * 32 + ac4);
    };
    auto LOADB = [&](int i) {
#pragma unroll
        for (int t = 0; t < BT4; ++t)
            rb[t] = *(const float4*)(B + (long)(arow + t * 32) * ldb + i * 32 + ac4);
    };
    auto STORE = [&](int s) {
        const uint32_t base = sb + (uint32_t)s * STG;
#pragma unroll
        for (int t = 0; t < 4; ++t) {
            uint32_t h0, l0, h1, l1;
            cvt_pair(ra[t].x * ascale, ra[t].y * ascale, h0, l0);
            cvt_pair(ra[t].z * ascale, ra[t].w * ascale, h1, l1);
            uint32_t off = (uint32_t)(arow + t * 32) * RB + (uint32_t)ac4 * 2;
            STS64(base + off, h0, h1);
            STS64(base + ASZ + off, l0, l1);
        }
#pragma unroll
        for (int t = 0; t < BT4; ++t) {
            uint32_t h0, l0, h1, l1;
            cvt_pair(rb[t].x, rb[t].y, h0, l0);
            cvt_pair(rb[t].z, rb[t].w, h1, l1);
            uint32_t off = (uint32_t)(arow + t * 32) * RB + (uint32_t)ac4 * 2;
            STS64(base + 2 * ASZ + off, h0, h1);
            STS64(base + 2 * ASZ + BSZ + off, l0, l1);
        }
    };

    const int NC = K / 32;
    LOADA(0); LOADB(0); STORE(0);
    __syncthreads();

    // ldmatrix per-lane fixed parts
    const int aRowF = wm + (lane & 7) + ((lane >> 3) & 1) * 8;   // + (mat&1)*8
    const uint32_t aColHalf = (uint32_t)((lane >> 4) * 8) * 2;   // (mat>>1)*8 cols
    const int l16 = lane & 15;
    const int bRowF = wn + (l16 & 7);
    const uint32_t bColHalf = (uint32_t)((l16 >> 3) * 8) * 2;

    for (int i = 0; i < NC; ++i) {
        const int s = i & 1;
        if (i + 1 < NC) { LOADA(i + 1); LOADB(i + 1); }

        const uint32_t aB = sb + (uint32_t)s * STG;
        const uint32_t bB = aB + 2 * ASZ;
#pragma unroll
        for (int ks = 0; ks < 2; ++ks) {
            uint32_t ah[4][4], al[4][4];
            const uint32_t acol = (uint32_t)(ks * 16) * 2 + aColHalf;
#pragma unroll
            for (int mt = 0; mt < 4; ++mt) {
                uint32_t ad = aB + (uint32_t)(aRowF + mt * 16) * RB + acol;
                ldsm4(ah[mt], ad);
                ldsm4(al[mt], ad + ASZ);
            }
            uint32_t bh[NTC][2], bl[NTC][2];
            const uint32_t bcol = (uint32_t)(ks * 16) * 2 + bColHalf;
#pragma unroll
            for (int nt = 0; nt < NTC; ++nt) {
                uint32_t bd = bB + (uint32_t)(bRowF + nt * 8) * RB + bcol;
                ldsm2(bh[nt], bd);
                ldsm2(bl[nt], bd + BSZ);
            }
#pragma unroll
            for (int mt = 0; mt < 4; ++mt)
#pragma unroll
                for (int nt = 0; nt < NTC; ++nt) {
                    mma16816(acc[mt][nt], ah[mt], bh[nt]);
                    mma16816(acc[mt][nt], al[mt], bh[nt]);
                    mma16816(acc[mt][nt], ah[mt], bl[nt]);
                }
        }
        if (i + 1 < NC) STORE(s ^ 1);
        __syncthreads();
    }

    // ---- epilogue ----
    auto ST = [&](int m, int n, float x, float y) {
        if (MODE == 0) {
            float* p = C + (long)blockIdx.z * sCz + (long)m * ldc + n;
            *(float2*)p = make_float2(x, y);
        } else if (MODE == 1) {
            int h = n >> 6, d = n & 63, b = m >> 10, sI = m & 1023;
            float* p = C + ((long)(b * HH + h) * SS + sI) * DD + d;
            *(float2*)p = make_float2(x, y);
        } else if (MODE == 2) {
            int h = n >> 6, d = n & 63, b = m >> 10, sI = m & 1023;
            float* p = C + ((long)(b * HH + h) * DD + d) * SS + sI;
            p[0] = x; p[SS] = y;
        } else {
            int z = blockIdx.z, b = z >> 4, h = z & 15;
            float* p = C + ((long)(b * SS + m)) * DMM + h * DD + n;
            *(float2*)p = make_float2(x, y);
        }
    };

#pragma unroll
    for (int mt = 0; mt < 4; ++mt)
#pragma unroll
        for (int nt = 0; nt < NTC; ++nt) {
            int r0 = m0 + wm + mt * 16 + (lane >> 2);
            int cn = n0 + wn + nt * 8 + (lane & 3) * 2;
            ST(r0,     cn, acc[mt][nt][0], acc[mt][nt][1]);
            ST(r0 + 8, cn, acc[mt][nt][2], acc[mt][nt][3]);
        }
}

// ---------------------------------------------------------------------------
// Row softmax in place (1024 per row)
// ---------------------------------------------------------------------------
__global__ void __launch_bounds__(256) softmax_rows(float* __restrict__ attn)
{
    const long row = blockIdx.x;
    float* p = attn + row * 1024;
    const int tid = threadIdx.x;
    float4 v = ((float4*)p)[tid];

    float m = fmaxf(fmaxf(v.x, v.y), fmaxf(v.z, v.w));
#pragma unroll
    for (int o = 16; o; o >>= 1) m = fmaxf(m, __shfl_xor_sync(0xffffffffu, m, o));

    __shared__ float sm[8], ssum[8];
    const int wid = tid >> 5, lid = tid & 31;
    if (lid == 0) sm[wid] = m;
    __syncthreads();
    float bm = sm[0];
#pragma unroll
    for (int i = 1; i < 8; ++i) bm = fmaxf(bm, sm[i]);

    float e0 = __expf(v.x - bm), e1 = __expf(v.y - bm);
    float e2 = __expf(v.z - bm), e3 = __expf(v.w - bm);
    float s = e0 + e1 + e2 + e3;
#pragma unroll
    for (int o = 16; o; o >>= 1) s += __shfl_xor_sync(0xffffffffu, s, o);
    if (lid == 0) ssum[wid] = s;
    __syncthreads();
    float bs = 0.f;
#pragma unroll
    for (int i = 0; i < 8; ++i) bs += ssum[i];

    float inv = 1.0f / bs;
    ((float4*)p)[tid] = make_float4(e0 * inv, e1 * inv, e2 * inv, e3 * inv);
}

// ---------------------------------------------------------------------------
extern "C" void kernel_launch(void* const* d_in, const int* in_sizes, int n_in,
                              void* d_out, int out_size)
{
    const float* query = (const float*)d_in[0];
    const float* key   = (const float*)d_in[1];
    const float* value = (const float*)d_in[2];
    const float* Wq    = (const float*)d_in[3];
    const float* Wk    = (const float*)d_in[4];
    const float* Wv    = (const float*)d_in[5];
    const float* Wo    = (const float*)d_in[6];
    float* out = (float*)d_out;

    float *Qp, *Kp, *Vtp, *Cp, *Ap;
    cudaGetSymbolAddress((void**)&Qp, g_Q);
    cudaGetSymbolAddress((void**)&Kp, g_K);
    cudaGetSymbolAddress((void**)&Vtp, g_Vt);
    cudaGetSymbolAddress((void**)&Cp, g_ctx);
    cudaGetSymbolAddress((void**)&Ap, g_attn);

    float* attn = ((size_t)out_size >= OUT_ELEMS + ATT_ELEMS) ? (out + OUT_ELEMS) : Ap;

    // dynamic smem: 2 stages of (A hi/lo + B hi/lo), padded rows of 80 B
    const int SM128 = 2 * (2 * 128 * 80 + 2 * 128 * 80);  // 81920
    const int SM64  = 2 * (2 * 128 * 80 + 2 * 64 * 80);   // 61440

    cudaFuncSetAttribute(gemm_mma<128, 0>, cudaFuncAttributeMaxDynamicSharedMemorySize, SM128);
    cudaFuncSetAttribute(gemm_mma<128, 1>, cudaFuncAttributeMaxDynamicSharedMemorySize, SM128);
    cudaFuncSetAttribute(gemm_mma<128, 2>, cudaFuncAttributeMaxDynamicSharedMemorySize, SM128);
    cudaFuncSetAttribute(gemm_mma<64, 3>,  cudaFuncAttributeMaxDynamicSharedMemorySize, SM64);

    dim3 blk(256);

    // Q/K projections -> [bh][s][d]
    gemm_mma<128, 1><<<dim3(8, 32, 1), blk, SM128>>>(query, Wq, Qp, DMM, DMM, DMM, 0, 0, 0, 0, 1.0f);
    gemm_mma<128, 1><<<dim3(8, 32, 1), blk, SM128>>>(key,   Wk, Kp, DMM, DMM, DMM, 0, 0, 0, 0, 1.0f);
    // V projection -> transposed [bh][d][s]
    gemm_mma<128, 2><<<dim3(8, 32, 1), blk, SM128>>>(value, Wv, Vtp, DMM, DMM, DMM, 0, 0, 0, 0, 1.0f);

    // scores = (Q/8) K^T, batched over 64 (b,h)
    gemm_mma<128, 0><<<dim3(8, 8, BB * HH), blk, SM128>>>(Qp, Kp, attn, DD, DD, DD, SS,
                                                          (long)SS * DD, (long)SS * DD,
                                                          (long)SS * SS, 0.125f);

    softmax_rows<<<BB * HH * SS, 256>>>(attn);

    // ctx = attn @ V  (B = V^T rows = d), scatter to [b,s,dm]
    gemm_mma<64, 3><<<dim3(1, 8, BB * HH), blk, SM64>>>(attn, Vtp, Cp, SS, SS, SS, 0,
                                                        (long)SS * SS, (long)DD * SS, 0, 1.0f);

    // out = ctx @ Wo^T
    gemm_mma<128, 0><<<dim3(8, 32, 1), blk, SM128>>>(Cp, Wo, out, DMM, DMM, DMM, DMM, 0, 0, 0, 1.0f);
}

// round 4
// speedup vs baseline: 1.8982x; 1.0326x over previous
#include <cuda_runtime.h>
#include <cuda_bf16.h>
#include <cstdint>

#define BB 4
#define SS 1024
#define HH 16
#define DD 64
#define DMM 1024

static const size_t OUT_ELEMS = (size_t)BB * SS * DMM;        // 4194304
static const size_t ATT_ELEMS = (size_t)BB * HH * SS * SS;    // 67108864

#define ACT_N (4096 * 1024)
#define W_N   (1024 * 1024)

// Scratch (__device__ globals: allocation-free rule) — all bf16 hi/lo pairs
__device__ __align__(16) __nv_bfloat16 g_XQh[ACT_N], g_XQl[ACT_N];
__device__ __align__(16) __nv_bfloat16 g_XKh[ACT_N], g_XKl[ACT_N];
__device__ __align__(16) __nv_bfloat16 g_XVh[ACT_N], g_XVl[ACT_N];
__device__ __align__(16) __nv_bfloat16 g_Wqh[W_N], g_Wql[W_N];
__device__ __align__(16) __nv_bfloat16 g_Wkh[W_N], g_Wkl[W_N];
__device__ __align__(16) __nv_bfloat16 g_Wvh[W_N], g_Wvl[W_N];
__device__ __align__(16) __nv_bfloat16 g_Woh[W_N], g_Wol[W_N];
__device__ __align__(16) __nv_bfloat16 g_Qh[ACT_N], g_Ql[ACT_N];   // [bh][s][d]
__device__ __align__(16) __nv_bfloat16 g_Kh[ACT_N], g_Kl[ACT_N];   // [bh][s][d]
__device__ __align__(16) __nv_bfloat16 g_Vth[ACT_N], g_Vtl[ACT_N]; // [bh][d][s]
__device__ __align__(16) __nv_bfloat16 g_Ch[ACT_N], g_Cl[ACT_N];   // ctx [b*s][dm]
__device__ float g_attn[(size_t)BB * HH * SS * SS];                 // fallback

// ---------------------------------------------------------------------------
__device__ __forceinline__ uint32_t smem_u32(const void* p) {
    uint32_t a;
    asm("{ .reg .u64 t; cvta.to.shared.u64 t, %1; cvt.u32.u64 %0, t; }" : "=r"(a) : "l"(p));
    return a;
}
__device__ __forceinline__ void ldsm4(uint32_t* r, uint32_t addr) {
    asm volatile("ldmatrix.sync.aligned.m8n8.x4.shared.b16 {%0,%1,%2,%3}, [%4];"
        : "=r"(r[0]), "=r"(r[1]), "=r"(r[2]), "=r"(r[3]) : "r"(addr));
}
__device__ __forceinline__ void mma16816(float* d, const uint32_t* a, uint32_t b0, uint32_t b1) {
    asm volatile("mma.sync.aligned.m16n8k16.row.col.f32.bf16.bf16.f32 "
        "{%0,%1,%2,%3}, {%4,%5,%6,%7}, {%8,%9}, {%0,%1,%2,%3};"
        : "+f"(d[0]), "+f"(d[1]), "+f"(d[2]), "+f"(d[3])
        : "r"(a[0]), "r"(a[1]), "r"(a[2]), "r"(a[3]), "r"(b0), "r"(b1));
}
__device__ __forceinline__ void cp16(uint32_t s, const void* g) {
    asm volatile("cp.async.cg.shared.global [%0], [%1], 16;" :: "r"(s), "l"(g));
}
#define CP_COMMIT() asm volatile("cp.async.commit_group;" ::: "memory")
#define STS128(addr, r0, r1, r2, r3) \
    asm volatile("st.shared.v4.b32 [%0], {%1,%2,%3,%4};" \
        :: "r"(addr), "r"(r0), "r"(r1), "r"(r2), "r"(r3) : "memory")

__device__ __forceinline__ void cvt_pair(float x, float y, uint32_t& hi, uint32_t& lo) {
    __nv_bfloat16 hx = __float2bfloat16(x), hy = __float2bfloat16(y);
    float rx = x - __bfloat162float(hx), ry = y - __bfloat162float(hy);
    __nv_bfloat16 lx = __float2bfloat16(rx), ly = __float2bfloat16(ry);
    hi = ((uint32_t)__bfloat16_as_ushort(hy) << 16) | __bfloat16_as_ushort(hx);
    lo = ((uint32_t)__bfloat16_as_ushort(ly) << 16) | __bfloat16_as_ushort(lx);
}

// ---------------------------------------------------------------------------
// Split fp32 -> bf16 hi/lo for all 7 inputs in one launch.
// f4 layout: [XQ 1M][XK 1M][XV 1M][Wq 256K][Wk 256K][Wv 256K][Wo 256K]
// ---------------------------------------------------------------------------
__global__ void __launch_bounds__(256) split_all(
    const float* q, const float* k, const float* v,
    const float* wq, const float* wk, const float* wv, const float* wo)
{
    long i4 = (long)blockIdx.x * blockDim.x + threadIdx.x;   // float4 index
    const float* src; __nv_bfloat16 *dh, *dl; long rel;
    const long M1 = 1048576, Q4 = 262144;
    if (i4 < M1)            { src = q;  dh = g_XQh; dl = g_XQl; rel = i4; }
    else if (i4 < 2*M1)     { src = k;  dh = g_XKh; dl = g_XKl; rel = i4 - M1; }
    else if (i4 < 3*M1)     { src = v;  dh = g_XVh; dl = g_XVl; rel = i4 - 2*M1; }
    else if (i4 < 3*M1+Q4)  { src = wq; dh = g_Wqh; dl = g_Wql; rel = i4 - 3*M1; }
    else if (i4 < 3*M1+2*Q4){ src = wk; dh = g_Wkh; dl = g_Wkl; rel = i4 - 3*M1 - Q4; }
    else if (i4 < 3*M1+3*Q4){ src = wv; dh = g_Wvh; dl = g_Wvl; rel = i4 - 3*M1 - 2*Q4; }
    else                    { src = wo; dh = g_Woh; dl = g_Wol; rel = i4 - 3*M1 - 3*Q4; }
    float4 x = ((const float4*)src)[rel];
    uint32_t h0, l0, h1, l1;
    cvt_pair(x.x, x.y, h0, l0);
    cvt_pair(x.z, x.w, h1, l1);
    ((uint2*)dh)[rel] = make_uint2(h0, h1);
    ((uint2*)dl)[rel] = make_uint2(l0, l1);
}

// ---------------------------------------------------------------------------
// Split-precision bf16 HMMA GEMM on pre-split hi/lo pairs.
// C[m][n] = sum_k A[m][k]*B[n][k] (NT form). Block tile 128 x NT, BK=32,
// 512 threads (16 warps, 4x4), warp tile 32 x (NT/4), cp.async double buffer.
// PAIRA=false: A is fp32 (attn), split in-loader.
// MODE: 0 fp32 row-major (*scale); 1 pair out [bh][s][d]; 2 pair out Vt
//       [bh][d][s]; 3 pair out ctx [b*s][dm] (z=bh, n=d)
// ---------------------------------------------------------------------------
template<int NT, int MODE, bool PAIRA>
__global__ void __launch_bounds__(512) gemm_pp(
    const __nv_bfloat16* __restrict__ Ah, const __nv_bfloat16* __restrict__ Al,
    const float* __restrict__ Af,
    const __nv_bfloat16* __restrict__ Bh, const __nv_bfloat16* __restrict__ Bl,
    float* __restrict__ Cf, __nv_bfloat16* __restrict__ Ch, __nv_bfloat16* __restrict__ Cl,
    int K, int lda, int ldb, int ldc,
    long sAz, long sBz, long sCz, float scale)
{
    extern __shared__ char smem[];
    constexpr int RB  = 80;
    constexpr int ASZ = 128 * RB;
    constexpr int BSZ = NT * RB;
    constexpr int STG = 2 * ASZ + 2 * BSZ;
    constexpr int NTP = (NT == 128) ? 2 : 1;   // B ldsm4 pairs per warp
    constexpr int WNE = (NT == 128) ? 32 : 16; // warp n extent

    const uint32_t sb = smem_u32(smem);
    const int tid = threadIdx.x, lane = tid & 31, wid = tid >> 5;
    const int wm = (wid & 3) * 32, wn = (wid >> 2) * WNE;
    const int m0 = blockIdx.y * 128, n0 = blockIdx.x * NT;

    if (PAIRA) {
        Ah += (long)blockIdx.z * sAz + (long)m0 * lda;
        Al += (long)blockIdx.z * sAz + (long)m0 * lda;
    } else {
        Af += (long)blockIdx.z * sAz + (long)m0 * lda;
    }
    Bh += (long)blockIdx.z * sBz + (long)n0 * ldb;
    Bl += (long)blockIdx.z * sBz + (long)n0 * ldb;

    float acc[2][2 * NTP][4];
#pragma unroll
    for (int mt = 0; mt < 2; ++mt)
#pragma unroll
        for (int nt = 0; nt < 2 * NTP; ++nt)
#pragma unroll
            for (int j = 0; j < 4; ++j) acc[mt][nt][j] = 0.f;

    const int row = tid >> 2, g = tid & 3;

    float4 ra[2];  // PAIRA=false staging: 8 floats

    auto CPA = [&](int i, int st) {
        const __nv_bfloat16* sh = Ah + (long)row * lda + i * 32 + g * 8;
        const __nv_bfloat16* sl = Al + (long)row * lda + i * 32 + g * 8;
        uint32_t d = sb + (uint32_t)st * STG + (uint32_t)row * RB + (uint32_t)g * 16;
        cp16(d, sh);
        cp16(d + ASZ, sl);
    };
    auto LDGA = [&](int i) {
        const float* s = Af + (long)row * lda + i * 32 + g * 8;
        ra[0] = *(const float4*)s;
        ra[1] = *(const float4*)(s + 4);
    };
    auto STSA = [&](int st) {
        uint32_t h[4], l[4];
        cvt_pair(ra[0].x, ra[0].y, h[0], l[0]);
        cvt_pair(ra[0].z, ra[0].w, h[1], l[1]);
        cvt_pair(ra[1].x, ra[1].y, h[2], l[2]);
        cvt_pair(ra[1].z, ra[1].w, h[3], l[3]);
        uint32_t d = sb + (uint32_t)st * STG + (uint32_t)row * RB + (uint32_t)g * 16;
        STS128(d, h[0], h[1], h[2], h[3]);
        STS128(d + ASZ, l[0], l[1], l[2], l[3]);
    };
    auto CPB = [&](int i, int st) {
        if (NT == 128 || tid < 256) {
            const __nv_bfloat16* sh = Bh + (long)row * ldb + i * 32 + g * 8;
            const __nv_bfloat16* sl = Bl + (long)row * ldb + i * 32 + g * 8;
            uint32_t d = sb + (uint32_t)st * STG + 2 * ASZ + (uint32_t)row * RB + (uint32_t)g * 16;
            cp16(d, sh);
            cp16(d + BSZ, sl);
        }
    };

    const int NC = K / 32;
    // prologue
    if (PAIRA) CPA(0, 0); else LDGA(0);
    CPB(0, 0);
    CP_COMMIT();
    if (!PAIRA) STSA(0);

    // per-lane ldsm offsets
    const int aRowOff = (lane & 7) + ((lane >> 3) & 1) * 8;
    const uint32_t aColOff = (uint32_t)((lane >> 4) * 8);
    const int bRowOff = (lane & 7) + ((lane >> 4) & 1) * 8;
    const uint32_t bColOff = (uint32_t)(((lane >> 3) & 1) * 8);

    for (int i = 0; i < NC; ++i) {
        const int s = i & 1;
        if (i + 1 < NC) {
            if (PAIRA) CPA(i + 1, s ^ 1); else LDGA(i + 1);
            CPB(i + 1, s ^ 1);
            CP_COMMIT();
            asm volatile("cp.async.wait_group 1;" ::: "memory");
        } else {
            asm volatile("cp.async.wait_group 0;" ::: "memory");
        }
        __syncthreads();

        const uint32_t aB = sb + (uint32_t)s * STG;
        const uint32_t bB = aB + 2 * ASZ;
#pragma unroll
        for (int ks = 0; ks < 2; ++ks) {
            uint32_t ah[2][4], al[2][4];
            const uint32_t ac = (aColOff + ks * 16) * 2;
#pragma unroll
            for (int mt = 0; mt < 2; ++mt) {
                uint32_t ad = aB + (uint32_t)(wm + mt * 16 + aRowOff) * RB + ac;
                ldsm4(ah[mt], ad);
                ldsm4(al[mt], ad + ASZ);
            }
            uint32_t bh[NTP][4], bl[NTP][4];
            const uint32_t bc = (bColOff + ks * 16) * 2;
#pragma unroll
            for (int p = 0; p < NTP; ++p) {
                uint32_t bd = bB + (uint32_t)(wn + p * 16 + bRowOff) * RB + bc;
                ldsm4(bh[p], bd);
                ldsm4(bl[p], bd + BSZ);
            }
#pragma unroll
            for (int mt = 0; mt < 2; ++mt)
#pragma unroll
                for (int p = 0; p < NTP; ++p) {
                    mma16816(acc[mt][2*p],   ah[mt], bh[p][0], bh[p][1]);
                    mma16816(acc[mt][2*p],   al[mt], bh[p][0], bh[p][1]);
                    mma16816(acc[mt][2*p],   ah[mt], bl[p][0], bl[p][1]);
                    mma16816(acc[mt][2*p+1], ah[mt], bh[p][2], bh[p][3]);
                    mma16816(acc[mt][2*p+1], al[mt], bh[p][2], bh[p][3]);
                    mma16816(acc[mt][2*p+1], ah[mt], bl[p][2], bl[p][3]);
                }
        }
        if (!PAIRA && i + 1 < NC) STSA(s ^ 1);
        __syncthreads();
    }

    // ---- epilogue ----
    auto emit = [&](int m, int n, float x, float y) {
        if (MODE == 0) {
            float* p = Cf + (long)blockIdx.z * sCz + (long)m * ldc + n;
            *(float2*)p = make_float2(x * scale, y * scale);
        } else if (MODE == 1) {
            int h = n >> 6, d = n & 63, b = m >> 10, sI = m & 1023;
            long idx = ((long)(b * HH + h) * SS + sI) * DD + d;
            uint32_t hi, lo;
            cvt_pair(x, y, hi, lo);
            *(uint32_t*)(Ch + idx) = hi;
            *(uint32_t*)(Cl + idx) = lo;
        } else if (MODE == 2) {
            int h = n >> 6, d = n & 63, b = m >> 10, sI = m & 1023;
            long base = ((long)(b * HH + h) * DD + d) * SS + sI;
            __nv_bfloat16 xh = __float2bfloat16(x);
            __nv_bfloat16 xl = __float2bfloat16(x - __bfloat162float(xh));
            __nv_bfloat16 yh = __float2bfloat16(y);
            __nv_bfloat16 yl = __float2bfloat16(y - __bfloat162float(yh));
            Ch[base] = xh; Cl[base] = xl;
            Ch[base + SS] = yh; Cl[base + SS] = yl;
        } else {
            int z = blockIdx.z, b = z >> 4, h = z & 15;
            long idx = ((long)(b * SS + m)) * DMM + h * DD + n;
            uint32_t hi, lo;
            cvt_pair(x, y, hi, lo);
            *(uint32_t*)(Ch + idx) = hi;
            *(uint32_t*)(Cl + idx) = lo;
        }
    };

#pragma unroll
    for (int mt = 0; mt < 2; ++mt)
#pragma unroll
        for (int nt = 0; nt < 2 * NTP; ++nt) {
            int m = m0 + wm + mt * 16 + (lane >> 2);
            int n = n0 + wn + nt * 8 + (lane & 3) * 2;
            emit(m,     n, acc[mt][nt][0], acc[mt][nt][1]);
            emit(m + 8, n, acc[mt][nt][2], acc[mt][nt][3]);
        }
}

// ---------------------------------------------------------------------------
// Row softmax in place (1024 per row)
// ---------------------------------------------------------------------------
__global__ void __launch_bounds__(256) softmax_rows(float* __restrict__ attn)
{
    const long row = blockIdx.x;
    float* p = attn + row * 1024;
    const int tid = threadIdx.x;
    float4 v = ((float4*)p)[tid];

    float m = fmaxf(fmaxf(v.x, v.y), fmaxf(v.z, v.w));
#pragma unroll
    for (int o = 16; o; o >>= 1) m = fmaxf(m, __shfl_xor_sync(0xffffffffu, m, o));

    __shared__ float sm[8], ssum[8];
    const int wid = tid >> 5, lid = tid & 31;
    if (lid == 0) sm[wid] = m;
    __syncthreads();
    float bm = sm[0];
#pragma unroll
    for (int i = 1; i < 8; ++i) bm = fmaxf(bm, sm[i]);

    float e0 = __expf(v.x - bm), e1 = __expf(v.y - bm);
    float e2 = __expf(v.z - bm), e3 = __expf(v.w - bm);
    float s = e0 + e1 + e2 + e3;
#pragma unroll
    for (int o = 16; o; o >>= 1) s += __shfl_xor_sync(0xffffffffu, s, o);
    if (lid == 0) ssum[wid] = s;
    __syncthreads();
    float bs = 0.f;
#pragma unroll
    for (int i = 0; i < 8; ++i) bs += ssum[i];

    float inv = 1.0f / bs;
    ((float4*)p)[tid] = make_float4(e0 * inv, e1 * inv, e2 * inv, e3 * inv);
}

// ---------------------------------------------------------------------------
extern "C" void kernel_launch(void* const* d_in, const int* in_sizes, int n_in,
                              void* d_out, int out_size)
{
    const float* query = (const float*)d_in[0];
    const float* key   = (const float*)d_in[1];
    const float* value = (const float*)d_in[2];
    const float* Wq    = (const float*)d_in[3];
    const float* Wk    = (const float*)d_in[4];
    const float* Wv    = (const float*)d_in[5];
    const float* Wo    = (const float*)d_in[6];
    float* out = (float*)d_out;

    __nv_bfloat16 *XQh, *XQl, *XKh, *XKl, *XVh, *XVl;
    __nv_bfloat16 *Wqh, *Wql, *Wkh, *Wkl, *Wvh, *Wvl, *Woh, *Wol;
    __nv_bfloat16 *Qh, *Ql, *Kh, *Kl, *Vth, *Vtl, *Chp, *Clp;
    float* Ap;
    cudaGetSymbolAddress((void**)&XQh, g_XQh); cudaGetSymbolAddress((void**)&XQl, g_XQl);
    cudaGetSymbolAddress((void**)&XKh, g_XKh); cudaGetSymbolAddress((void**)&XKl, g_XKl);
    cudaGetSymbolAddress((void**)&XVh, g_XVh); cudaGetSymbolAddress((void**)&XVl, g_XVl);
    cudaGetSymbolAddress((void**)&Wqh, g_Wqh); cudaGetSymbolAddress((void**)&Wql, g_Wql);
    cudaGetSymbolAddress((void**)&Wkh, g_Wkh); cudaGetSymbolAddress((void**)&Wkl, g_Wkl);
    cudaGetSymbolAddress((void**)&Wvh, g_Wvh); cudaGetSymbolAddress((void**)&Wvl, g_Wvl);
    cudaGetSymbolAddress((void**)&Woh, g_Woh); cudaGetSymbolAddress((void**)&Wol, g_Wol);
    cudaGetSymbolAddress((void**)&Qh, g_Qh);   cudaGetSymbolAddress((void**)&Ql, g_Ql);
    cudaGetSymbolAddress((void**)&Kh, g_Kh);   cudaGetSymbolAddress((void**)&Kl, g_Kl);
    cudaGetSymbolAddress((void**)&Vth, g_Vth); cudaGetSymbolAddress((void**)&Vtl, g_Vtl);
    cudaGetSymbolAddress((void**)&Chp, g_Ch);  cudaGetSymbolAddress((void**)&Clp, g_Cl);
    cudaGetSymbolAddress((void**)&Ap, g_attn);

    float* attn = ((size_t)out_size >= OUT_ELEMS + ATT_ELEMS) ? (out + OUT_ELEMS) : Ap;

    const int SM128 = 2 * (2 * 128 * 80 + 2 * 128 * 80);  // 81920
    const int SM64  = 2 * (2 * 128 * 80 + 2 * 64 * 80);   // 61440
    cudaFuncSetAttribute(gemm_pp<128, 1, true>, cudaFuncAttributeMaxDynamicSharedMemorySize, SM128);
    cudaFuncSetAttribute(gemm_pp<128, 2, true>, cudaFuncAttributeMaxDynamicSharedMemorySize, SM128);
    cudaFuncSetAttribute(gemm_pp<128, 0, true>, cudaFuncAttributeMaxDynamicSharedMemorySize, SM128);
    cudaFuncSetAttribute(gemm_pp<64, 3, false>, cudaFuncAttributeMaxDynamicSharedMemorySize, SM64);

    // 1) split all fp32 inputs to bf16 hi/lo (4M float4 total)
    split_all<<<16384, 256>>>(query, key, value, Wq, Wk, Wv, Wo);

    dim3 blk(512);

    // 2) projections (pure pair GEMMs)
    gemm_pp<128, 1, true><<<dim3(8, 32, 1), blk, SM128>>>(
        XQh, XQl, nullptr, Wqh, Wql, nullptr, Qh, Ql,
        DMM, DMM, DMM, 0, 0, 0, 0, 1.0f);
    gemm_pp<128, 1, true><<<dim3(8, 32, 1), blk, SM128>>>(
        XKh, XKl, nullptr, Wkh, Wkl, nullptr, Kh, Kl,
        DMM, DMM, DMM, 0, 0, 0, 0, 1.0f);
    gemm_pp<128, 2, true><<<dim3(8, 32, 1), blk, SM128>>>(
        XVh, XVl, nullptr, Wvh, Wvl, nullptr, Vth, Vtl,
        DMM, DMM, DMM, 0, 0, 0, 0, 1.0f);

    // 3) scores = (Q K^T)/8
    gemm_pp<128, 0, true><<<dim3(8, 8, BB * HH), blk, SM128>>>(
        Qh, Ql, nullptr, Kh, Kl, attn, nullptr, nullptr,
        DD, DD, DD, SS, (long)SS * DD, (long)SS * DD, (long)SS * SS, 0.125f);

    // 4) softmax in place
    softmax_rows<<<BB * HH * SS, 256>>>(attn);

    // 5) ctx = attn @ V  (A fp32 in-loader split, B = Vt pair) -> ctx pair
    gemm_pp<64, 3, false><<<dim3(1, 8, BB * HH), blk, SM64>>>(
        nullptr, nullptr, attn, Vth, Vtl, nullptr, Chp, Clp,
        SS, SS, SS, 0, (long)SS * SS, (long)DD * SS, 0, 1.0f);

    // 6) out = ctx @ Wo^T
    gemm_pp<128, 0, true><<<dim3(8, 32, 1), blk, SM128>>>(
        Chp, Clp, nullptr, Woh, Wol, out, nullptr, nullptr,
        DMM, DMM, DMM, DMM, 0, 0, 0, 1.0f);
}

// round 5
// speedup vs baseline: 1.9433x; 1.0238x over previous
#include <cuda_runtime.h>
#include <cuda_bf16.h>
#include <cstdint>

#define BB 4
#define SS 1024
#define HH 16
#define DD 64
#define DMM 1024

static const size_t OUT_ELEMS = (size_t)BB * SS * DMM;        // 4194304
static const size_t ATT_ELEMS = (size_t)BB * HH * SS * SS;    // 67108864

#define ACT_N (4096 * 1024)
#define W_N   (1024 * 1024)

// Scratch (__device__ globals: allocation-free rule) — all bf16 hi/lo pairs
__device__ __align__(16) __nv_bfloat16 g_XQh[ACT_N], g_XQl[ACT_N];
__device__ __align__(16) __nv_bfloat16 g_XKh[ACT_N], g_XKl[ACT_N];
__device__ __align__(16) __nv_bfloat16 g_XVh[ACT_N], g_XVl[ACT_N];
__device__ __align__(16) __nv_bfloat16 g_Wqh[W_N], g_Wql[W_N];
__device__ __align__(16) __nv_bfloat16 g_Wkh[W_N], g_Wkl[W_N];
__device__ __align__(16) __nv_bfloat16 g_Wvh[W_N], g_Wvl[W_N];
__device__ __align__(16) __nv_bfloat16 g_Woh[W_N], g_Wol[W_N];
__device__ __align__(16) __nv_bfloat16 g_Qh[ACT_N], g_Ql[ACT_N];   // [bh][s][d]
__device__ __align__(16) __nv_bfloat16 g_Kh[ACT_N], g_Kl[ACT_N];   // [bh][s][d]
__device__ __align__(16) __nv_bfloat16 g_Vth[ACT_N], g_Vtl[ACT_N]; // [bh][d][s]
__device__ __align__(16) __nv_bfloat16 g_Ch[ACT_N], g_Cl[ACT_N];   // ctx [b*s][dm]
__device__ float g_attn[(size_t)BB * HH * SS * SS];                 // fallback

// ---------------------------------------------------------------------------
__device__ __forceinline__ uint32_t smem_u32(const void* p) {
    uint32_t a;
    asm("{ .reg .u64 t; cvta.to.shared.u64 t, %1; cvt.u32.u64 %0, t; }" : "=r"(a) : "l"(p));
    return a;
}
__device__ __forceinline__ void ldsm4(uint32_t* r, uint32_t addr) {
    asm volatile("ldmatrix.sync.aligned.m8n8.x4.shared.b16 {%0,%1,%2,%3}, [%4];"
        : "=r"(r[0]), "=r"(r[1]), "=r"(r[2]), "=r"(r[3]) : "r"(addr));
}
__device__ __forceinline__ void mma16816(float* d, const uint32_t* a, uint32_t b0, uint32_t b1) {
    asm volatile("mma.sync.aligned.m16n8k16.row.col.f32.bf16.bf16.f32 "
        "{%0,%1,%2,%3}, {%4,%5,%6,%7}, {%8,%9}, {%0,%1,%2,%3};"
        : "+f"(d[0]), "+f"(d[1]), "+f"(d[2]), "+f"(d[3])
        : "r"(a[0]), "r"(a[1]), "r"(a[2]), "r"(a[3]), "r"(b0), "r"(b1));
}
__device__ __forceinline__ void cp16(uint32_t s, const void* g) {
    asm volatile("cp.async.cg.shared.global [%0], [%1], 16;" :: "r"(s), "l"(g));
}
#define CP_COMMIT() asm volatile("cp.async.commit_group;" ::: "memory")
#define STS128(addr, r0, r1, r2, r3) \
    asm volatile("st.shared.v4.b32 [%0], {%1,%2,%3,%4};" \
        :: "r"(addr), "r"(r0), "r"(r1), "r"(r2), "r"(r3) : "memory")

__device__ __forceinline__ void cvt_pair(float x, float y, uint32_t& hi, uint32_t& lo) {
    __nv_bfloat16 hx = __float2bfloat16(x), hy = __float2bfloat16(y);
    float rx = x - __bfloat162float(hx), ry = y - __bfloat162float(hy);
    __nv_bfloat16 lx = __float2bfloat16(rx), ly = __float2bfloat16(ry);
    hi = ((uint32_t)__bfloat16_as_ushort(hy) << 16) | __bfloat16_as_ushort(hx);
    lo = ((uint32_t)__bfloat16_as_ushort(ly) << 16) | __bfloat16_as_ushort(lx);
}

// ---------------------------------------------------------------------------
// Split fp32 -> bf16 hi/lo for all 7 inputs in one launch.
// ---------------------------------------------------------------------------
__global__ void __launch_bounds__(256) split_all(
    const float* q, const float* k, const float* v,
    const float* wq, const float* wk, const float* wv, const float* wo)
{
    long i4 = (long)blockIdx.x * blockDim.x + threadIdx.x;   // float4 index
    const float* src; __nv_bfloat16 *dh, *dl; long rel;
    const long M1 = 1048576, Q4 = 262144;
    if (i4 < M1)            { src = q;  dh = g_XQh; dl = g_XQl; rel = i4; }
    else if (i4 < 2*M1)     { src = k;  dh = g_XKh; dl = g_XKl; rel = i4 - M1; }
    else if (i4 < 3*M1)     { src = v;  dh = g_XVh; dl = g_XVl; rel = i4 - 2*M1; }
    else if (i4 < 3*M1+Q4)  { src = wq; dh = g_Wqh; dl = g_Wql; rel = i4 - 3*M1; }
    else if (i4 < 3*M1+2*Q4){ src = wk; dh = g_Wkh; dl = g_Wkl; rel = i4 - 3*M1 - Q4; }
    else if (i4 < 3*M1+3*Q4){ src = wv; dh = g_Wvh; dl = g_Wvl; rel = i4 - 3*M1 - 2*Q4; }
    else                    { src = wo; dh = g_Woh; dl = g_Wol; rel = i4 - 3*M1 - 3*Q4; }
    float4 x = ((const float4*)src)[rel];
    uint32_t h0, l0, h1, l1;
    cvt_pair(x.x, x.y, h0, l0);
    cvt_pair(x.z, x.w, h1, l1);
    ((uint2*)dh)[rel] = make_uint2(h0, h1);
    ((uint2*)dl)[rel] = make_uint2(l0, l1);
}

// ---------------------------------------------------------------------------
// Split-precision bf16 HMMA GEMM on pre-split hi/lo pairs.
// 128 x NT block tile, BK=32, 512 threads (4x4 warps), 3-stage cp.async
// pipeline, ONE __syncthreads per chunk, pass-major MMA issue order.
// ---------------------------------------------------------------------------
template<int NT, int MODE, bool PAIRA>
__global__ void __launch_bounds__(512) gemm_pp(
    const __nv_bfloat16* __restrict__ Ah, const __nv_bfloat16* __restrict__ Al,
    const float* __restrict__ Af,
    const __nv_bfloat16* __restrict__ Bh, const __nv_bfloat16* __restrict__ Bl,
    float* __restrict__ Cf, __nv_bfloat16* __restrict__ Ch, __nv_bfloat16* __restrict__ Cl,
    int K, int lda, int ldb, int ldc,
    long sAz, long sBz, long sCz, float scale)
{
    extern __shared__ char smem[];
    constexpr int RB  = 80;
    constexpr int ASZ = 128 * RB;
    constexpr int BSZ = NT * RB;
    constexpr int STG = 2 * ASZ + 2 * BSZ;
    constexpr int NTP = (NT == 128) ? 2 : 1;
    constexpr int WNE = (NT == 128) ? 32 : 16;
    constexpr int NST = 3;                        // pipeline stages

    const uint32_t sb = smem_u32(smem);
    const int tid = threadIdx.x, lane = tid & 31, wid = tid >> 5;
    const int wm = (wid & 3) * 32, wn = (wid >> 2) * WNE;
    const int m0 = blockIdx.y * 128, n0 = blockIdx.x * NT;

    if (PAIRA) {
        Ah += (long)blockIdx.z * sAz + (long)m0 * lda;
        Al += (long)blockIdx.z * sAz + (long)m0 * lda;
    } else {
        Af += (long)blockIdx.z * sAz + (long)m0 * lda;
    }
    Bh += (long)blockIdx.z * sBz + (long)n0 * ldb;
    Bl += (long)blockIdx.z * sBz + (long)n0 * ldb;

    float acc[2][2 * NTP][4];
#pragma unroll
    for (int mt = 0; mt < 2; ++mt)
#pragma unroll
        for (int nt = 0; nt < 2 * NTP; ++nt)
#pragma unroll
            for (int j = 0; j < 4; ++j) acc[mt][nt][j] = 0.f;

    const int row = tid >> 2, g = tid & 3;
    float4 ra[2];

    auto CPA = [&](int i, int st) {
        const __nv_bfloat16* sh = Ah + (long)row * lda + i * 32 + g * 8;
        const __nv_bfloat16* sl = Al + (long)row * lda + i * 32 + g * 8;
        uint32_t d = sb + (uint32_t)st * STG + (uint32_t)row * RB + (uint32_t)g * 16;
        cp16(d, sh);
        cp16(d + ASZ, sl);
    };
    auto LDGA = [&](int i) {
        const float* s = Af + (long)row * lda + i * 32 + g * 8;
        ra[0] = *(const float4*)s;
        ra[1] = *(const float4*)(s + 4);
    };
    auto STSA = [&](int st) {
        uint32_t h[4], l[4];
        cvt_pair(ra[0].x, ra[0].y, h[0], l[0]);
        cvt_pair(ra[0].z, ra[0].w, h[1], l[1]);
        cvt_pair(ra[1].x, ra[1].y, h[2], l[2]);
        cvt_pair(ra[1].z, ra[1].w, h[3], l[3]);
        uint32_t d = sb + (uint32_t)st * STG + (uint32_t)row * RB + (uint32_t)g * 16;
        STS128(d, h[0], h[1], h[2], h[3]);
        STS128(d + ASZ, l[0], l[1], l[2], l[3]);
    };
    auto CPB = [&](int i, int st) {
        if (NT == 128 || tid < 256) {
            const __nv_bfloat16* sh = Bh + (long)row * ldb + i * 32 + g * 8;
            const __nv_bfloat16* sl = Bl + (long)row * ldb + i * 32 + g * 8;
            uint32_t d = sb + (uint32_t)st * STG + 2 * ASZ + (uint32_t)row * RB + (uint32_t)g * 16;
            cp16(d, sh);
            cp16(d + BSZ, sl);
        }
    };

    const int NC = K / 32;

    // prologue: fill NST-1 stages (one commit group per stage)
#pragma unroll
    for (int st = 0; st < NST - 1; ++st) {
        if (st < NC) {
            if (PAIRA) CPA(st, st); else LDGA(st);
            CPB(st, st);
            CP_COMMIT();
            if (!PAIRA) STSA(st);
        }
    }

    // per-lane ldsm offsets
    const int aRowOff = (lane & 7) + ((lane >> 3) & 1) * 8;
    const uint32_t aColOff = (uint32_t)((lane >> 4) * 8);
    const int bRowOff = (lane & 7) + ((lane >> 4) & 1) * 8;
    const uint32_t bColOff = (uint32_t)(((lane >> 3) & 1) * 8);

    for (int i = 0; i < NC; ++i) {
        const int s = i % NST;
        if (i == NC - 1) asm volatile("cp.async.wait_group 0;" ::: "memory");
        else             asm volatile("cp.async.wait_group 1;" ::: "memory");
        __syncthreads();

        const uint32_t aB = sb + (uint32_t)s * STG;
        const uint32_t bB = aB + 2 * ASZ;
#pragma unroll
        for (int ks = 0; ks < 2; ++ks) {
            uint32_t ah[2][4], al[2][4];
            const uint32_t ac = (aColOff + ks * 16) * 2;
#pragma unroll
            for (int mt = 0; mt < 2; ++mt) {
                uint32_t ad = aB + (uint32_t)(wm + mt * 16 + aRowOff) * RB + ac;
                ldsm4(ah[mt], ad);
                ldsm4(al[mt], ad + ASZ);
            }
            uint32_t bh[NTP][4], bl[NTP][4];
            const uint32_t bc = (bColOff + ks * 16) * 2;
#pragma unroll
            for (int p = 0; p < NTP; ++p) {
                uint32_t bd = bB + (uint32_t)(wn + p * 16 + bRowOff) * RB + bc;
                ldsm4(bh[p], bd);
                ldsm4(bl[p], bd + BSZ);
            }
            // pass-major: 8 independent MMAs per pass (distinct accumulators)
#pragma unroll
            for (int mt = 0; mt < 2; ++mt)
#pragma unroll
                for (int p = 0; p < NTP; ++p) {
                    mma16816(acc[mt][2*p],   ah[mt], bh[p][0], bh[p][1]);
                    mma16816(acc[mt][2*p+1], ah[mt], bh[p][2], bh[p][3]);
                }
#pragma unroll
            for (int mt = 0; mt < 2; ++mt)
#pragma unroll
                for (int p = 0; p < NTP; ++p) {
                    mma16816(acc[mt][2*p],   al[mt], bh[p][0], bh[p][1]);
                    mma16816(acc[mt][2*p+1], al[mt], bh[p][2], bh[p][3]);
                }
#pragma unroll
            for (int mt = 0; mt < 2; ++mt)
#pragma unroll
                for (int p = 0; p < NTP; ++p) {
                    mma16816(acc[mt][2*p],   ah[mt], bl[p][0], bl[p][1]);
                    mma16816(acc[mt][2*p+1], ah[mt], bl[p][2], bl[p][3]);
                }
        }

        // prefetch stage i+NST-1 into slot (i-1)%NST (safe: all warps passed sync_i)
        const int nf = i + NST - 1;
        if (nf < NC) {
            const int sf = nf % NST;
            if (PAIRA) CPA(nf, sf); else LDGA(nf);
            CPB(nf, sf);
            CP_COMMIT();
            if (!PAIRA) STSA(sf);
        }
    }

    // ---- epilogue ----
    auto emit = [&](int m, int n, float x, float y) {
        if (MODE == 0) {
            float* p = Cf + (long)blockIdx.z * sCz + (long)m * ldc + n;
            *(float2*)p = make_float2(x * scale, y * scale);
        } else if (MODE == 1) {
            int h = n >> 6, d = n & 63, b = m >> 10, sI = m & 1023;
            long idx = ((long)(b * HH + h) * SS + sI) * DD + d;
            uint32_t hi, lo;
            cvt_pair(x, y, hi, lo);
            *(uint32_t*)(Ch + idx) = hi;
            *(uint32_t*)(Cl + idx) = lo;
        } else if (MODE == 2) {
            int h = n >> 6, d = n & 63, b = m >> 10, sI = m & 1023;
            long base = ((long)(b * HH + h) * DD + d) * SS + sI;
            __nv_bfloat16 xh = __float2bfloat16(x);
            __nv_bfloat16 xl = __float2bfloat16(x - __bfloat162float(xh));
            __nv_bfloat16 yh = __float2bfloat16(y);
            __nv_bfloat16 yl = __float2bfloat16(y - __bfloat162float(yh));
            Ch[base] = xh; Cl[base] = xl;
            Ch[base + SS] = yh; Cl[base + SS] = yl;
        } else {
            int z = blockIdx.z, b = z >> 4, h = z & 15;
            long idx = ((long)(b * SS + m)) * DMM + h * DD + n;
            uint32_t hi, lo;
            cvt_pair(x, y, hi, lo);
            *(uint32_t*)(Ch + idx) = hi;
            *(uint32_t*)(Cl + idx) = lo;
        }
    };

#pragma unroll
    for (int mt = 0; mt < 2; ++mt)
#pragma unroll
        for (int nt = 0; nt < 2 * NTP; ++nt) {
            int m = m0 + wm + mt * 16 + (lane >> 2);
            int n = n0 + wn + nt * 8 + (lane & 3) * 2;
            emit(m,     n, acc[mt][nt][0], acc[mt][nt][1]);
            emit(m + 8, n, acc[mt][nt][2], acc[mt][nt][3]);
        }
}

// ---------------------------------------------------------------------------
// Row softmax in place (1024 per row)
// ---------------------------------------------------------------------------
__global__ void __launch_bounds__(256) softmax_rows(float* __restrict__ attn)
{
    const long row = blockIdx.x;
    float* p = attn + row * 1024;
    const int tid = threadIdx.x;
    float4 v = ((float4*)p)[tid];

    float m = fmaxf(fmaxf(v.x, v.y), fmaxf(v.z, v.w));
#pragma unroll
    for (int o = 16; o; o >>= 1) m = fmaxf(m, __shfl_xor_sync(0xffffffffu, m, o));

    __shared__ float sm[8], ssum[8];
    const int wid = tid >> 5, lid = tid & 31;
    if (lid == 0) sm[wid] = m;
    __syncthreads();
    float bm = sm[0];
#pragma unroll
    for (int i = 1; i < 8; ++i) bm = fmaxf(bm, sm[i]);

    float e0 = __expf(v.x - bm), e1 = __expf(v.y - bm);
    float e2 = __expf(v.z - bm), e3 = __expf(v.w - bm);
    float s = e0 + e1 + e2 + e3;
#pragma unroll
    for (int o = 16; o; o >>= 1) s += __shfl_xor_sync(0xffffffffu, s, o);
    if (lid == 0) ssum[wid] = s;
    __syncthreads();
    float bs = 0.f;
#pragma unroll
    for (int i = 0; i < 8; ++i) bs += ssum[i];

    float inv = 1.0f / bs;
    ((float4*)p)[tid] = make_float4(e0 * inv, e1 * inv, e2 * inv, e3 * inv);
}

// ---------------------------------------------------------------------------
extern "C" void kernel_launch(void* const* d_in, const int* in_sizes, int n_in,
                              void* d_out, int out_size)
{
    const float* query = (const float*)d_in[0];
    const float* key   = (const float*)d_in[1];
    const float* value = (const float*)d_in[2];
    const float* Wq    = (const float*)d_in[3];
    const float* Wk    = (const float*)d_in[4];
    const float* Wv    = (const float*)d_in[5];
    const float* Wo    = (const float*)d_in[6];
    float* out = (float*)d_out;

    __nv_bfloat16 *XQh, *XQl, *XKh, *XKl, *XVh, *XVl;
    __nv_bfloat16 *Wqh, *Wql, *Wkh, *Wkl, *Wvh, *Wvl, *Woh, *Wol;
    __nv_bfloat16 *Qh, *Ql, *Kh, *Kl, *Vth, *Vtl, *Chp, *Clp;
    float* Ap;
    cudaGetSymbolAddress((void**)&XQh, g_XQh); cudaGetSymbolAddress((void**)&XQl, g_XQl);
    cudaGetSymbolAddress((void**)&XKh, g_XKh); cudaGetSymbolAddress((void**)&XKl, g_XKl);
    cudaGetSymbolAddress((void**)&XVh, g_XVh); cudaGetSymbolAddress((void**)&XVl, g_XVl);
    cudaGetSymbolAddress((void**)&Wqh, g_Wqh); cudaGetSymbolAddress((void**)&Wql, g_Wql);
    cudaGetSymbolAddress((void**)&Wkh, g_Wkh); cudaGetSymbolAddress((void**)&Wkl, g_Wkl);
    cudaGetSymbolAddress((void**)&Wvh, g_Wvh); cudaGetSymbolAddress((void**)&Wvl, g_Wvl);
    cudaGetSymbolAddress((void**)&Woh, g_Woh); cudaGetSymbolAddress((void**)&Wol, g_Wol);
    cudaGetSymbolAddress((void**)&Qh, g_Qh);   cudaGetSymbolAddress((void**)&Ql, g_Ql);
    cudaGetSymbolAddress((void**)&Kh, g_Kh);   cudaGetSymbolAddress((void**)&Kl, g_Kl);
    cudaGetSymbolAddress((void**)&Vth, g_Vth); cudaGetSymbolAddress((void**)&Vtl, g_Vtl);
    cudaGetSymbolAddress((void**)&Chp, g_Ch);  cudaGetSymbolAddress((void**)&Clp, g_Cl);
    cudaGetSymbolAddress((void**)&Ap, g_attn);

    float* attn = ((size_t)out_size >= OUT_ELEMS + ATT_ELEMS) ? (out + OUT_ELEMS) : Ap;

    const int SM128 = 3 * (2 * 128 * 80 + 2 * 128 * 80);  // 122880
    const int SM64  = 3 * (2 * 128 * 80 + 2 * 64 * 80);   // 92160
    cudaFuncSetAttribute(gemm_pp<128, 1, true>, cudaFuncAttributeMaxDynamicSharedMemorySize, SM128);
    cudaFuncSetAttribute(gemm_pp<128, 2, true>, cudaFuncAttributeMaxDynamicSharedMemorySize, SM128);
    cudaFuncSetAttribute(gemm_pp<128, 0, true>, cudaFuncAttributeMaxDynamicSharedMemorySize, SM128);
    cudaFuncSetAttribute(gemm_pp<64, 3, false>, cudaFuncAttributeMaxDynamicSharedMemorySize, SM64);

    // 1) split all fp32 inputs to bf16 hi/lo
    split_all<<<16384, 256>>>(query, key, value, Wq, Wk, Wv, Wo);

    dim3 blk(512);

    // 2) projections
    gemm_pp<128, 1, true><<<dim3(8, 32, 1), blk, SM128>>>(
        XQh, XQl, nullptr, Wqh, Wql, nullptr, Qh, Ql,
        DMM, DMM, DMM, 0, 0, 0, 0, 1.0f);
    gemm_pp<128, 1, true><<<dim3(8, 32, 1), blk, SM128>>>(
        XKh, XKl, nullptr, Wkh, Wkl, nullptr, Kh, Kl,
        DMM, DMM, DMM, 0, 0, 0, 0, 1.0f);
    gemm_pp<128, 2, true><<<dim3(8, 32, 1), blk, SM128>>>(
        XVh, XVl, nullptr, Wvh, Wvl, nullptr, Vth, Vtl,
        DMM, DMM, DMM, 0, 0, 0, 0, 1.0f);

    // 3) scores = (Q K^T)/8
    gemm_pp<128, 0, true><<<dim3(8, 8, BB * HH), blk, SM128>>>(
        Qh, Ql, nullptr, Kh, Kl, attn, nullptr, nullptr,
        DD, DD, DD, SS, (long)SS * DD, (long)SS * DD, (long)SS * SS, 0.125f);

    // 4) softmax in place
    softmax_rows<<<BB * HH * SS, 256>>>(attn);

    // 5) ctx = attn @ V
    gemm_pp<64, 3, false><<<dim3(1, 8, BB * HH), blk, SM64>>>(
        nullptr, nullptr, attn, Vth, Vtl, nullptr, Chp, Clp,
        SS, SS, SS, 0, (long)SS * SS, (long)DD * SS, 0, 1.0f);

    // 6) out = ctx @ Wo^T
    gemm_pp<128, 0, true><<<dim3(8, 32, 1), blk, SM128>>>(
        Chp, Clp, nullptr, Woh, Wol, out, nullptr, nullptr,
        DMM, DMM, DMM, DMM, 0, 0, 0, 1.0f);
}

// round 7
// speedup vs baseline: 2.0136x; 1.0362x over previous
#include <cuda_runtime.h>
#include <cuda_bf16.h>
#include <cstdint>

#define BB 4
#define SS 1024
#define HH 16
#define DD 64
#define DMM 1024

static const size_t OUT_ELEMS = (size_t)BB * SS * DMM;        // 4194304
static const size_t ATT_ELEMS = (size_t)BB * HH * SS * SS;    // 67108864

#define ACT_N (4096 * 1024)
#define W_N   (1024 * 1024)

// Scratch (__device__ globals) — all bf16 hi/lo pairs
__device__ __align__(16) __nv_bfloat16 g_XQh[ACT_N], g_XQl[ACT_N];
__device__ __align__(16) __nv_bfloat16 g_XKh[ACT_N], g_XKl[ACT_N];
__device__ __align__(16) __nv_bfloat16 g_XVh[ACT_N], g_XVl[ACT_N];
__device__ __align__(16) __nv_bfloat16 g_Wqh[W_N], g_Wql[W_N];
__device__ __align__(16) __nv_bfloat16 g_Wkh[W_N], g_Wkl[W_N];
__device__ __align__(16) __nv_bfloat16 g_Wvh[W_N], g_Wvl[W_N];
__device__ __align__(16) __nv_bfloat16 g_Woh[W_N], g_Wol[W_N];
__device__ __align__(16) __nv_bfloat16 g_Qh[ACT_N], g_Ql[ACT_N];   // [bh][s][d]
__device__ __align__(16) __nv_bfloat16 g_Kh[ACT_N], g_Kl[ACT_N];   // [bh][s][d]
__device__ __align__(16) __nv_bfloat16 g_Vth[ACT_N], g_Vtl[ACT_N]; // [bh][d][s]
__device__ __align__(16) __nv_bfloat16 g_Ch[ACT_N], g_Cl[ACT_N];   // ctx [b*s][dm]
__device__ float g_attn[(size_t)BB * HH * SS * SS];                 // fallback

// ---------------------------------------------------------------------------
__device__ __forceinline__ uint32_t smem_u32(const void* p) {
    uint32_t a;
    asm("{ .reg .u64 t; cvta.to.shared.u64 t, %1; cvt.u32.u64 %0, t; }" : "=r"(a) : "l"(p));
    return a;
}
__device__ __forceinline__ void ldsm4(uint32_t* r, uint32_t addr) {
    asm volatile("ldmatrix.sync.aligned.m8n8.x4.shared.b16 {%0,%1,%2,%3}, [%4];"
        : "=r"(r[0]), "=r"(r[1]), "=r"(r[2]), "=r"(r[3]) : "r"(addr));
}
__device__ __forceinline__ void mma16816(float* d, const uint32_t* a, uint32_t b0, uint32_t b1) {
    asm volatile("mma.sync.aligned.m16n8k16.row.col.f32.bf16.bf16.f32 "
        "{%0,%1,%2,%3}, {%4,%5,%6,%7}, {%8,%9}, {%0,%1,%2,%3};"
        : "+f"(d[0]), "+f"(d[1]), "+f"(d[2]), "+f"(d[3])
        : "r"(a[0]), "r"(a[1]), "r"(a[2]), "r"(a[3]), "r"(b0), "r"(b1));
}
__device__ __forceinline__ void cp16(uint32_t s, const void* g) {
    asm volatile("cp.async.cg.shared.global [%0], [%1], 16;" :: "r"(s), "l"(g));
}
#define CP_COMMIT() asm volatile("cp.async.commit_group;" ::: "memory")
#define CP_WAIT(N)  asm volatile("cp.async.wait_group %0;" :: "n"(N) : "memory")
#define STS64(addr, r0, r1) \
    asm volatile("st.shared.v2.b32 [%0], {%1,%2};" :: "r"(addr), "r"(r0), "r"(r1) : "memory")

__device__ __forceinline__ void cvt_pair(float x, float y, uint32_t& hi, uint32_t& lo) {
    __nv_bfloat16 hx = __float2bfloat16(x), hy = __float2bfloat16(y);
    float rx = x - __bfloat162float(hx), ry = y - __bfloat162float(hy);
    __nv_bfloat16 lx = __float2bfloat16(rx), ly = __float2bfloat16(ry);
    hi = ((uint32_t)__bfloat16_as_ushort(hy) << 16) | __bfloat16_as_ushort(hx);
    lo = ((uint32_t)__bfloat16_as_ushort(ly) << 16) | __bfloat16_as_ushort(lx);
}

// ---------------------------------------------------------------------------
// Split fp32 -> bf16 hi/lo for all 7 inputs in one launch.
// ---------------------------------------------------------------------------
__global__ void __launch_bounds__(256) split_all(
    const float* q, const float* k, const float* v,
    const float* wq, const float* wk, const float* wv, const float* wo)
{
    long i4 = (long)blockIdx.x * blockDim.x + threadIdx.x;   // float4 index
    const float* src; __nv_bfloat16 *dh, *dl; long rel;
    const long M1 = 1048576, Q4 = 262144;
    if (i4 < M1)            { src = q;  dh = g_XQh; dl = g_XQl; rel = i4; }
    else if (i4 < 2*M1)     { src = k;  dh = g_XKh; dl = g_XKl; rel = i4 - M1; }
    else if (i4 < 3*M1)     { src = v;  dh = g_XVh; dl = g_XVl; rel = i4 - 2*M1; }
    else if (i4 < 3*M1+Q4)  { src = wq; dh = g_Wqh; dl = g_Wql; rel = i4 - 3*M1; }
    else if (i4 < 3*M1+2*Q4){ src = wk; dh = g_Wkh; dl = g_Wkl; rel = i4 - 3*M1 - Q4; }
    else if (i4 < 3*M1+3*Q4){ src = wv; dh = g_Wvh; dl = g_Wvl; rel = i4 - 3*M1 - 2*Q4; }
    else                    { src = wo; dh = g_Woh; dl = g_Wol; rel = i4 - 3*M1 - 3*Q4; }
    float4 x = ((const float4*)src)[rel];
    uint32_t h0, l0, h1, l1;
    cvt_pair(x.x, x.y, h0, l0);
    cvt_pair(x.z, x.w, h1, l1);
    ((uint2*)dh)[rel] = make_uint2(h0, h1);
    ((uint2*)dl)[rel] = make_uint2(l0, l1);
}

// ---------------------------------------------------------------------------
// Split-precision bf16 HMMA GEMM on pre-split hi/lo pairs.
// 128 x NT block tile, BK=32, 256 threads (8 warps, 2Mx4N), warp tile 64x(NT/4),
// 2-stage cp.async pipeline (2 CTAs/SM). Correct barrier protocol:
//   prefetch -> wait_group(1) -> sync (visibility) -> compute -> STSA -> sync (retire)
// ---------------------------------------------------------------------------
template<int NT, int MODE, bool PAIRA>
__global__ void __launch_bounds__(256) gemm_pp(
    const __nv_bfloat16* __restrict__ Ah, const __nv_bfloat16* __restrict__ Al,
    const float* __restrict__ Af,
    const __nv_bfloat16* __restrict__ Bh, const __nv_bfloat16* __restrict__ Bl,
    float* __restrict__ Cf, __nv_bfloat16* __restrict__ Ch, __nv_bfloat16* __restrict__ Cl,
    int K, int lda, int ldb, int ldc,
    long sAz, long sBz, long sCz, float scale)
{
    extern __shared__ char smem[];
    constexpr int RB  = 80;
    constexpr int ASZ = 128 * RB;                 // 10240 per part
    constexpr int BSZ = NT * RB;
    constexpr int STG = 2 * ASZ + 2 * BSZ;
    constexpr int NTP = (NT == 128) ? 2 : 1;      // B ldsm4 groups per warp
    constexpr int WNE = (NT == 128) ? 32 : 16;    // warp n extent

    const uint32_t sb = smem_u32(smem);
    const int tid = threadIdx.x, lane = tid & 31, wid = tid >> 5;
    const int wm = (wid & 1) * 64, wn = (wid >> 1) * WNE;
    const int m0 = blockIdx.y * 128, n0 = blockIdx.x * NT;

    if (PAIRA) {
        Ah += (long)blockIdx.z * sAz + (long)m0 * lda;
        Al += (long)blockIdx.z * sAz + (long)m0 * lda;
    } else {
        Af += (long)blockIdx.z * sAz + (long)m0 * lda;
    }
    Bh += (long)blockIdx.z * sBz + (long)n0 * ldb;
    Bl += (long)blockIdx.z * sBz + (long)n0 * ldb;

    float acc[4][2 * NTP][4];
#pragma unroll
    for (int mt = 0; mt < 4; ++mt)
#pragma unroll
        for (int nt = 0; nt < 2 * NTP; ++nt)
#pragma unroll
            for (int j = 0; j < 4; ++j) acc[mt][nt][j] = 0.f;

    float4 ra[4];  // fp32-A staging (PAIRA=false)

    auto CPA = [&](int i, int st) {
#pragma unroll
        for (int t = 0; t < 2; ++t) {
            int c = tid + t * 256, r = c >> 2, g = c & 3;
            uint32_t d = sb + (uint32_t)st * STG + (uint32_t)r * RB + (uint32_t)g * 16;
            cp16(d, Ah + (long)r * lda + i * 32 + g * 8);
            cp16(d + ASZ, Al + (long)r * lda + i * 32 + g * 8);
        }
    };
    auto CPB = [&](int i, int st) {
#pragma unroll
        for (int t = 0; t < (NT == 128 ? 2 : 1); ++t) {
            int c = tid + t * 256, r = c >> 2, g = c & 3;
            uint32_t d = sb + (uint32_t)st * STG + 2 * ASZ + (uint32_t)r * RB + (uint32_t)g * 16;
            cp16(d, Bh + (long)r * ldb + i * 32 + g * 8);
            cp16(d + BSZ, Bl + (long)r * ldb + i * 32 + g * 8);
        }
    };
    auto LDGA = [&](int i) {
#pragma unroll
        for (int t = 0; t < 4; ++t) {
            int c = tid + t * 256, r = c >> 3, g = c & 7;
            ra[t] = *(const float4*)(Af + (long)r * lda + i * 32 + g * 4);
        }
    };
    auto STSA = [&](int st) {
#pragma unroll
        for (int t = 0; t < 4; ++t) {
            int c = tid + t * 256, r = c >> 3, g = c & 7;
            uint32_t h0, l0, h1, l1;
            cvt_pair(ra[t].x, ra[t].y, h0, l0);
            cvt_pair(ra[t].z, ra[t].w, h1, l1);
            uint32_t d = sb + (uint32_t)st * STG + (uint32_t)r * RB + (uint32_t)g * 8;
            STS64(d, h0, h1);
            STS64(d + ASZ, l0, l1);
        }
    };

    const int NC = K / 32;

    // prologue: stage 0
    if (PAIRA) CPA(0, 0); else LDGA(0);
    CPB(0, 0);
    CP_COMMIT();
    if (!PAIRA) STSA(0);

    // per-lane ldsm offsets
    const int aRowOff = (lane & 7) + ((lane >> 3) & 1) * 8;
    const uint32_t aColOff = (uint32_t)((lane >> 4) * 8);
    const int bRowOff = (lane & 7) + ((lane >> 4) & 1) * 8;
    const uint32_t bColOff = (uint32_t)(((lane >> 3) & 1) * 8);

    for (int i = 0; i < NC; ++i) {
        const int s = i & 1;
        // prefetch next chunk into stage s^1 (stage s^1 readers finished at
        // the retire-sync of iter i-1)
        if (i + 1 < NC) {
            if (PAIRA) CPA(i + 1, s ^ 1);
            else       LDGA(i + 1);
            CPB(i + 1, s ^ 1);
            CP_COMMIT();
            CP_WAIT(1);    // stage s groups landed (newest may be pending)
        } else {
            CP_WAIT(0);
        }
        __syncthreads();   // visibility of stage s to all threads

        const uint32_t aB = sb + (uint32_t)s * STG;
        const uint32_t bB = aB + 2 * ASZ;
#pragma unroll
        for (int ks = 0; ks < 2; ++ks) {
            uint32_t ah[4][4], al[4][4];
            const uint32_t ac = (aColOff + ks * 16) * 2;
#pragma unroll
            for (int mt = 0; mt < 4; ++mt) {
                uint32_t ad = aB + (uint32_t)(wm + mt * 16 + aRowOff) * RB + ac;
                ldsm4(ah[mt], ad);
                ldsm4(al[mt], ad + ASZ);
            }
            uint32_t bh[NTP][4], bl[NTP][4];
            const uint32_t bc = (bColOff + ks * 16) * 2;
#pragma unroll
            for (int p = 0; p < NTP; ++p) {
                uint32_t bd = bB + (uint32_t)(wn + p * 16 + bRowOff) * RB + bc;
                ldsm4(bh[p], bd);
                ldsm4(bl[p], bd + BSZ);
            }
            // pass-major: 8*NTP independent MMAs per pass
#pragma unroll
            for (int mt = 0; mt < 4; ++mt)
#pragma unroll
                for (int p = 0; p < NTP; ++p) {
                    mma16816(acc[mt][2*p],   ah[mt], bh[p][0], bh[p][1]);
                    mma16816(acc[mt][2*p+1], ah[mt], bh[p][2], bh[p][3]);
                }
#pragma unroll
            for (int mt = 0; mt < 4; ++mt)
#pragma unroll
                for (int p = 0; p < NTP; ++p) {
                    mma16816(acc[mt][2*p],   al[mt], bh[p][0], bh[p][1]);
                    mma16816(acc[mt][2*p+1], al[mt], bh[p][2], bh[p][3]);
                }
#pragma unroll
            for (int mt = 0; mt < 4; ++mt)
#pragma unroll
                for (int p = 0; p < NTP; ++p) {
                    mma16816(acc[mt][2*p],   ah[mt], bl[p][0], bl[p][1]);
                    mma16816(acc[mt][2*p+1], ah[mt], bl[p][2], bl[p][3]);
                }
        }
        if (!PAIRA && i + 1 < NC) STSA(s ^ 1);
        __syncthreads();   // retire stage s (next iter prefetches into it)
    }

    // ---- epilogue ----
    auto emit = [&](int m, int n, float x, float y) {
        if (MODE == 0) {
            float* p = Cf + (long)blockIdx.z * sCz + (long)m * ldc + n;
            *(float2*)p = make_float2(x * scale, y * scale);
        } else if (MODE == 1) {
            int h = n >> 6, d = n & 63, b = m >> 10, sI = m & 1023;
            long idx = ((long)(b * HH + h) * SS + sI) * DD + d;
            uint32_t hi, lo;
            cvt_pair(x, y, hi, lo);
            *(uint32_t*)(Ch + idx) = hi;
            *(uint32_t*)(Cl + idx) = lo;
        } else if (MODE == 2) {
            int h = n >> 6, d = n & 63, b = m >> 10, sI = m & 1023;
            long base = ((long)(b * HH + h) * DD + d) * SS + sI;
            __nv_bfloat16 xh = __float2bfloat16(x);
            __nv_bfloat16 xl = __float2bfloat16(x - __bfloat162float(xh));
            __nv_bfloat16 yh = __float2bfloat16(y);
            __nv_bfloat16 yl = __float2bfloat16(y - __bfloat162float(yh));
            Ch[base] = xh; Cl[base] = xl;
            Ch[base + SS] = yh; Cl[base + SS] = yl;
        } else {
            int z = blockIdx.z, b = z >> 4, h = z & 15;
            long idx = ((long)(b * SS + m)) * DMM + h * DD + n;
            uint32_t hi, lo;
            cvt_pair(x, y, hi, lo);
            *(uint32_t*)(Ch + idx) = hi;
            *(uint32_t*)(Cl + idx) = lo;
        }
    };

#pragma unroll
    for (int mt = 0; mt < 4; ++mt)
#pragma unroll
        for (int nt = 0; nt < 2 * NTP; ++nt) {
            int m = m0 + wm + mt * 16 + (lane >> 2);
            int n = n0 + wn + nt * 8 + (lane & 3) * 2;
            emit(m,     n, acc[mt][nt][0], acc[mt][nt][1]);
            emit(m + 8, n, acc[mt][nt][2], acc[mt][nt][3]);
        }
}

// ---------------------------------------------------------------------------
// Row softmax in place (1024 per row)
// ---------------------------------------------------------------------------
__global__ void __launch_bounds__(256) softmax_rows(float* __restrict__ attn)
{
    const long row = blockIdx.x;
    float* p = attn + row * 1024;
    const int tid = threadIdx.x;
    float4 v = ((float4*)p)[tid];

    float m = fmaxf(fmaxf(v.x, v.y), fmaxf(v.z, v.w));
#pragma unroll
    for (int o = 16; o; o >>= 1) m = fmaxf(m, __shfl_xor_sync(0xffffffffu, m, o));

    __shared__ float sm[8], ssum[8];
    const int wid = tid >> 5, lid = tid & 31;
    if (lid == 0) sm[wid] = m;
    __syncthreads();
    float bm = sm[0];
#pragma unroll
    for (int i = 1; i < 8; ++i) bm = fmaxf(bm, sm[i]);

    float e0 = __expf(v.x - bm), e1 = __expf(v.y - bm);
    float e2 = __expf(v.z - bm), e3 = __expf(v.w - bm);
    float s = e0 + e1 + e2 + e3;
#pragma unroll
    for (int o = 16; o; o >>= 1) s += __shfl_xor_sync(0xffffffffu, s, o);
    if (lid == 0) ssum[wid] = s;
    __syncthreads();
    float bs = 0.f;
#pragma unroll
    for (int i = 0; i < 8; ++i) bs += ssum[i];

    float inv = 1.0f / bs;
    ((float4*)p)[tid] = make_float4(e0 * inv, e1 * inv, e2 * inv, e3 * inv);
}

// ---------------------------------------------------------------------------
extern "C" void kernel_launch(void* const* d_in, const int* in_sizes, int n_in,
                              void* d_out, int out_size)
{
    const float* query = (const float*)d_in[0];
    const float* key   = (const float*)d_in[1];
    const float* value = (const float*)d_in[2];
    const float* Wq    = (const float*)d_in[3];
    const float* Wk    = (const float*)d_in[4];
    const float* Wv    = (const float*)d_in[5];
    const float* Wo    = (const float*)d_in[6];
    float* out = (float*)d_out;

    __nv_bfloat16 *XQh, *XQl, *XKh, *XKl, *XVh, *XVl;
    __nv_bfloat16 *Wqh, *Wql, *Wkh, *Wkl, *Wvh, *Wvl, *Woh, *Wol;
    __nv_bfloat16 *Qh, *Ql, *Kh, *Kl, *Vth, *Vtl, *Chp, *Clp;
    float* Ap;
    cudaGetSymbolAddress((void**)&XQh, g_XQh); cudaGetSymbolAddress((void**)&XQl, g_XQl);
    cudaGetSymbolAddress((void**)&XKh, g_XKh); cudaGetSymbolAddress((void**)&XKl, g_XKl);
    cudaGetSymbolAddress((void**)&XVh, g_XVh); cudaGetSymbolAddress((void**)&XVl, g_XVl);
    cudaGetSymbolAddress((void**)&Wqh, g_Wqh); cudaGetSymbolAddress((void**)&Wql, g_Wql);
    cudaGetSymbolAddress((void**)&Wkh, g_Wkh); cudaGetSymbolAddress((void**)&Wkl, g_Wkl);
    cudaGetSymbolAddress((void**)&Wvh, g_Wvh); cudaGetSymbolAddress((void**)&Wvl, g_Wvl);
    cudaGetSymbolAddress((void**)&Woh, g_Woh); cudaGetSymbolAddress((void**)&Wol, g_Wol);
    cudaGetSymbolAddress((void**)&Qh, g_Qh);   cudaGetSymbolAddress((void**)&Ql, g_Ql);
    cudaGetSymbolAddress((void**)&Kh, g_Kh);   cudaGetSymbolAddress((void**)&Kl, g_Kl);
    cudaGetSymbolAddress((void**)&Vth, g_Vth); cudaGetSymbolAddress((void**)&Vtl, g_Vtl);
    cudaGetSymbolAddress((void**)&Chp, g_Ch);  cudaGetSymbolAddress((void**)&Clp, g_Cl);
    cudaGetSymbolAddress((void**)&Ap, g_attn);

    float* attn = ((size_t)out_size >= OUT_ELEMS + ATT_ELEMS) ? (out + OUT_ELEMS) : Ap;

    const int SM128 = 2 * (2 * 128 * 80 + 2 * 128 * 80);  // 81920
    const int SM64  = 2 * (2 * 128 * 80 + 2 * 64 * 80);   // 61440
    cudaFuncSetAttribute(gemm_pp<128, 1, true>, cudaFuncAttributeMaxDynamicSharedMemorySize, SM128);
    cudaFuncSetAttribute(gemm_pp<128, 2, true>, cudaFuncAttributeMaxDynamicSharedMemorySize, SM128);
    cudaFuncSetAttribute(gemm_pp<128, 0, true>, cudaFuncAttributeMaxDynamicSharedMemorySize, SM128);
    cudaFuncSetAttribute(gemm_pp<64, 3, false>, cudaFuncAttributeMaxDynamicSharedMemorySize, SM64);

    // 1) split all fp32 inputs to bf16 hi/lo
    split_all<<<16384, 256>>>(query, key, value, Wq, Wk, Wv, Wo);

    dim3 blk(256);

    // 2) projections
    gemm_pp<128, 1, true><<<dim3(8, 32, 1), blk, SM128>>>(
        XQh, XQl, nullptr, Wqh, Wql, nullptr, Qh, Ql,
        DMM, DMM, DMM, 0, 0, 0, 0, 1.0f);
    gemm_pp<128, 1, true><<<dim3(8, 32, 1), blk, SM128>>>(
        XKh, XKl, nullptr, Wkh, Wkl, nullptr, Kh, Kl,
        DMM, DMM, DMM, 0, 0, 0, 0, 1.0f);
    gemm_pp<128, 2, true><<<dim3(8, 32, 1), blk, SM128>>>(
        XVh, XVl, nullptr, Wvh, Wvl, nullptr, Vth, Vtl,
        DMM, DMM, DMM, 0, 0, 0, 0, 1.0f);

    // 3) scores = (Q K^T)/8
    gemm_pp<128, 0, true><<<dim3(8, 8, BB * HH), blk, SM128>>>(
        Qh, Ql, nullptr, Kh, Kl, attn, nullptr, nullptr,
        DD, DD, DD, SS, (long)SS * DD, (long)SS * DD, (long)SS * SS, 0.125f);

    // 4) softmax in place
    softmax_rows<<<BB * HH * SS, 256>>>(attn);

    // 5) ctx = attn @ V
    gemm_pp<64, 3, false><<<dim3(1, 8, BB * HH), blk, SM64>>>(
        nullptr, nullptr, attn, Vth, Vtl, nullptr, Chp, Clp,
        SS, SS, SS, 0, (long)SS * SS, (long)DD * SS, 0, 1.0f);

    // 6) out = ctx @ Wo^T
    gemm_pp<128, 0, true><<<dim3(8, 32, 1), blk, SM128>>>(
        Chp, Clp, nullptr, Woh, Wol, out, nullptr, nullptr,
        DMM, DMM, DMM, DMM, 0, 0, 0, 1.0f);
}

// round 8
// speedup vs baseline: 2.0388x; 1.0125x over previous
#include <cuda_runtime.h>
#include <cuda_bf16.h>
#include <cstdint>

#define BB 4
#define SS 1024
#define HH 16
#define DD 64
#define DMM 1024

static const size_t OUT_ELEMS = (size_t)BB * SS * DMM;        // 4194304
static const size_t ATT_ELEMS = (size_t)BB * HH * SS * SS;    // 67108864

#define ACT_N (4096 * 1024)
#define W_N   (1024 * 1024)

// Scratch (__device__ globals) — all bf16 hi/lo pairs
__device__ __align__(16) __nv_bfloat16 g_XQh[ACT_N], g_XQl[ACT_N];
__device__ __align__(16) __nv_bfloat16 g_XKh[ACT_N], g_XKl[ACT_N];
__device__ __align__(16) __nv_bfloat16 g_XVh[ACT_N], g_XVl[ACT_N];
__device__ __align__(16) __nv_bfloat16 g_Wqh[W_N], g_Wql[W_N];
__device__ __align__(16) __nv_bfloat16 g_Wkh[W_N], g_Wkl[W_N];
__device__ __align__(16) __nv_bfloat16 g_Wvh[W_N], g_Wvl[W_N];
__device__ __align__(16) __nv_bfloat16 g_Woh[W_N], g_Wol[W_N];
__device__ __align__(16) __nv_bfloat16 g_Qh[ACT_N], g_Ql[ACT_N];   // [bh][s][d]
__device__ __align__(16) __nv_bfloat16 g_Kh[ACT_N], g_Kl[ACT_N];   // [bh][s][d]
__device__ __align__(16) __nv_bfloat16 g_Vth[ACT_N], g_Vtl[ACT_N]; // [bh][d][s]
__device__ __align__(16) __nv_bfloat16 g_Ch[ACT_N], g_Cl[ACT_N];   // ctx [b*s][dm]
__device__ float g_attn[(size_t)BB * HH * SS * SS];                 // fallback

// ---------------------------------------------------------------------------
__device__ __forceinline__ uint32_t smem_u32(const void* p) {
    uint32_t a;
    asm("{ .reg .u64 t; cvta.to.shared.u64 t, %1; cvt.u32.u64 %0, t; }" : "=r"(a) : "l"(p));
    return a;
}
__device__ __forceinline__ void ldsm4(uint32_t* r, uint32_t addr) {
    asm volatile("ldmatrix.sync.aligned.m8n8.x4.shared.b16 {%0,%1,%2,%3}, [%4];"
        : "=r"(r[0]), "=r"(r[1]), "=r"(r[2]), "=r"(r[3]) : "r"(addr));
}
__device__ __forceinline__ void mma16816(float* d, const uint32_t* a, uint32_t b0, uint32_t b1) {
    asm volatile("mma.sync.aligned.m16n8k16.row.col.f32.bf16.bf16.f32 "
        "{%0,%1,%2,%3}, {%4,%5,%6,%7}, {%8,%9}, {%0,%1,%2,%3};"
        : "+f"(d[0]), "+f"(d[1]), "+f"(d[2]), "+f"(d[3])
        : "r"(a[0]), "r"(a[1]), "r"(a[2]), "r"(a[3]), "r"(b0), "r"(b1));
}
__device__ __forceinline__ void cp16(uint32_t s, const void* g) {
    asm volatile("cp.async.cg.shared.global [%0], [%1], 16;" :: "r"(s), "l"(g));
}
#define CP_COMMIT() asm volatile("cp.async.commit_group;" ::: "memory")
#define CP_WAIT(N)  asm volatile("cp.async.wait_group %0;" :: "n"(N) : "memory")
#define STS64(addr, r0, r1) \
    asm volatile("st.shared.v2.b32 [%0], {%1,%2};" :: "r"(addr), "r"(r0), "r"(r1) : "memory")

__device__ __forceinline__ void cvt_pair(float x, float y, uint32_t& hi, uint32_t& lo) {
    __nv_bfloat16 hx = __float2bfloat16(x), hy = __float2bfloat16(y);
    float rx = x - __bfloat162float(hx), ry = y - __bfloat162float(hy);
    __nv_bfloat16 lx = __float2bfloat16(rx), ly = __float2bfloat16(ry);
    hi = ((uint32_t)__bfloat16_as_ushort(hy) << 16) | __bfloat16_as_ushort(hx);
    lo = ((uint32_t)__bfloat16_as_ushort(ly) << 16) | __bfloat16_as_ushort(lx);
}

// ---------------------------------------------------------------------------
// Split fp32 -> bf16 hi/lo for all 7 inputs in one launch.
// ---------------------------------------------------------------------------
__global__ void __launch_bounds__(256) split_all(
    const float* q, const float* k, const float* v,
    const float* wq, const float* wk, const float* wv, const float* wo)
{
    long i4 = (long)blockIdx.x * blockDim.x + threadIdx.x;   // float4 index
    const float* src; __nv_bfloat16 *dh, *dl; long rel;
    const long M1 = 1048576, Q4 = 262144;
    if (i4 < M1)            { src = q;  dh = g_XQh; dl = g_XQl; rel = i4; }
    else if (i4 < 2*M1)     { src = k;  dh = g_XKh; dl = g_XKl; rel = i4 - M1; }
    else if (i4 < 3*M1)     { src = v;  dh = g_XVh; dl = g_XVl; rel = i4 - 2*M1; }
    else if (i4 < 3*M1+Q4)  { src = wq; dh = g_Wqh; dl = g_Wql; rel = i4 - 3*M1; }
    else if (i4 < 3*M1+2*Q4){ src = wk; dh = g_Wkh; dl = g_Wkl; rel = i4 - 3*M1 - Q4; }
    else if (i4 < 3*M1+3*Q4){ src = wv; dh = g_Wvh; dl = g_Wvl; rel = i4 - 3*M1 - 2*Q4; }
    else                    { src = wo; dh = g_Woh; dl = g_Wol; rel = i4 - 3*M1 - 3*Q4; }
    float4 x = ((const float4*)src)[rel];
    uint32_t h0, l0, h1, l1;
    cvt_pair(x.x, x.y, h0, l0);
    cvt_pair(x.z, x.w, h1, l1);
    ((uint2*)dh)[rel] = make_uint2(h0, h1);
    ((uint2*)dl)[rel] = make_uint2(l0, l1);
}

// ---------------------------------------------------------------------------
// Split-precision bf16 HMMA GEMM on pre-split hi/lo pairs.
// 128 x NT block tile, BK=32, 512 threads (16 warps, 4Mx4N), warp tile
// 32 x (NT/4), 2-stage cp.async pipeline, __launch_bounds__(512,2) so
// 2 CTAs/SM (32 warps/SM). Proven barrier protocol:
//   prefetch -> wait_group(1) -> sync -> compute -> STSA -> sync
// ---------------------------------------------------------------------------
template<int NT, int MODE, bool PAIRA>
__global__ void __launch_bounds__(512, 2) gemm_pp(
    const __nv_bfloat16* __restrict__ Ah, const __nv_bfloat16* __restrict__ Al,
    const float* __restrict__ Af,
    const __nv_bfloat16* __restrict__ Bh, const __nv_bfloat16* __restrict__ Bl,
    float* __restrict__ Cf, __nv_bfloat16* __restrict__ Ch, __nv_bfloat16* __restrict__ Cl,
    int K, int lda, int ldb, int ldc,
    long sAz, long sBz, long sCz, float scale)
{
    extern __shared__ char smem[];
    constexpr int RB  = 80;
    constexpr int ASZ = 128 * RB;                 // 10240 per part
    constexpr int BSZ = NT * RB;
    constexpr int STG = 2 * ASZ + 2 * BSZ;
    constexpr int NTP = (NT == 128) ? 2 : 1;      // B ldsm4 groups per warp
    constexpr int WNE = (NT == 128) ? 32 : 16;    // warp n extent

    const uint32_t sb = smem_u32(smem);
    const int tid = threadIdx.x, lane = tid & 31, wid = tid >> 5;
    const int wm = (wid & 3) * 32, wn = (wid >> 2) * WNE;
    const int m0 = blockIdx.y * 128, n0 = blockIdx.x * NT;

    if (PAIRA) {
        Ah += (long)blockIdx.z * sAz + (long)m0 * lda;
        Al += (long)blockIdx.z * sAz + (long)m0 * lda;
    } else {
        Af += (long)blockIdx.z * sAz + (long)m0 * lda;
    }
    Bh += (long)blockIdx.z * sBz + (long)n0 * ldb;
    Bl += (long)blockIdx.z * sBz + (long)n0 * ldb;

    float acc[2][2 * NTP][4];
#pragma unroll
    for (int mt = 0; mt < 2; ++mt)
#pragma unroll
        for (int nt = 0; nt < 2 * NTP; ++nt)
#pragma unroll
            for (int j = 0; j < 4; ++j) acc[mt][nt][j] = 0.f;

    float4 ra[2];  // fp32-A staging (PAIRA=false)

    auto CPA = [&](int i, int st) {
        int r = tid >> 2, g = tid & 3;            // 512 threads cover 128x4
        uint32_t d = sb + (uint32_t)st * STG + (uint32_t)r * RB + (uint32_t)g * 16;
        cp16(d, Ah + (long)r * lda + i * 32 + g * 8);
        cp16(d + ASZ, Al + (long)r * lda + i * 32 + g * 8);
    };
    auto CPB = [&](int i, int st) {
        if (NT == 128 || tid < 256) {
            int r = tid >> 2, g = tid & 3;
            uint32_t d = sb + (uint32_t)st * STG + 2 * ASZ + (uint32_t)r * RB + (uint32_t)g * 16;
            cp16(d, Bh + (long)r * ldb + i * 32 + g * 8);
            cp16(d + BSZ, Bl + (long)r * ldb + i * 32 + g * 8);
        }
    };
    auto LDGA = [&](int i) {
#pragma unroll
        for (int t = 0; t < 2; ++t) {
            int c = tid + t * 512, r = c >> 3, g = c & 7;
            ra[t] = *(const float4*)(Af + (long)r * lda + i * 32 + g * 4);
        }
    };
    auto STSA = [&](int st) {
#pragma unroll
        for (int t = 0; t < 2; ++t) {
            int c = tid + t * 512, r = c >> 3, g = c & 7;
            uint32_t h0, l0, h1, l1;
            cvt_pair(ra[t].x, ra[t].y, h0, l0);
            cvt_pair(ra[t].z, ra[t].w, h1, l1);
            uint32_t d = sb + (uint32_t)st * STG + (uint32_t)r * RB + (uint32_t)g * 8;
            STS64(d, h0, h1);
            STS64(d + ASZ, l0, l1);
        }
    };

    const int NC = K / 32;

    // prologue: stage 0
    if (PAIRA) CPA(0, 0); else LDGA(0);
    CPB(0, 0);
    CP_COMMIT();
    if (!PAIRA) STSA(0);

    // per-lane ldsm offsets
    const int aRowOff = (lane & 7) + ((lane >> 3) & 1) * 8;
    const uint32_t aColOff = (uint32_t)((lane >> 4) * 8);
    const int bRowOff = (lane & 7) + ((lane >> 4) & 1) * 8;
    const uint32_t bColOff = (uint32_t)(((lane >> 3) & 1) * 8);

    for (int i = 0; i < NC; ++i) {
        const int s = i & 1;
        if (i + 1 < NC) {
            if (PAIRA) CPA(i + 1, s ^ 1);
            else       LDGA(i + 1);
            CPB(i + 1, s ^ 1);
            CP_COMMIT();
            CP_WAIT(1);    // stage s landed (newest group may be pending)
        } else {
            CP_WAIT(0);
        }
        __syncthreads();   // visibility of stage s

        const uint32_t aB = sb + (uint32_t)s * STG;
        const uint32_t bB = aB + 2 * ASZ;
#pragma unroll
        for (int ks = 0; ks < 2; ++ks) {
            uint32_t ah[2][4], al[2][4];
            const uint32_t ac = (aColOff + ks * 16) * 2;
#pragma unroll
            for (int mt = 0; mt < 2; ++mt) {
                uint32_t ad = aB + (uint32_t)(wm + mt * 16 + aRowOff) * RB + ac;
                ldsm4(ah[mt], ad);
                ldsm4(al[mt], ad + ASZ);
            }
            uint32_t bh[NTP][4], bl[NTP][4];
            const uint32_t bc = (bColOff + ks * 16) * 2;
#pragma unroll
            for (int p = 0; p < NTP; ++p) {
                uint32_t bd = bB + (uint32_t)(wn + p * 16 + bRowOff) * RB + bc;
                ldsm4(bh[p], bd);
                ldsm4(bl[p], bd + BSZ);
            }
            // pass-major: 4*NTP independent MMAs per pass
#pragma unroll
            for (int mt = 0; mt < 2; ++mt)
#pragma unroll
                for (int p = 0; p < NTP; ++p) {
                    mma16816(acc[mt][2*p],   ah[mt], bh[p][0], bh[p][1]);
                    mma16816(acc[mt][2*p+1], ah[mt], bh[p][2], bh[p][3]);
                }
#pragma unroll
            for (int mt = 0; mt < 2; ++mt)
#pragma unroll
                for (int p = 0; p < NTP; ++p) {
                    mma16816(acc[mt][2*p],   al[mt], bh[p][0], bh[p][1]);
                    mma16816(acc[mt][2*p+1], al[mt], bh[p][2], bh[p][3]);
                }
#pragma unroll
            for (int mt = 0; mt < 2; ++mt)
#pragma unroll
                for (int p = 0; p < NTP; ++p) {
                    mma16816(acc[mt][2*p],   ah[mt], bl[p][0], bl[p][1]);
                    mma16816(acc[mt][2*p+1], ah[mt], bl[p][2], bl[p][3]);
                }
        }
        if (!PAIRA && i + 1 < NC) STSA(s ^ 1);
        __syncthreads();   // retire stage s
    }

    // ---- epilogue ----
    auto emit = [&](int m, int n, float x, float y) {
        if (MODE == 0) {
            float* p = Cf + (long)blockIdx.z * sCz + (long)m * ldc + n;
            *(float2*)p = make_float2(x * scale, y * scale);
        } else if (MODE == 1) {
            int h = n >> 6, d = n & 63, b = m >> 10, sI = m & 1023;
            long idx = ((long)(b * HH + h) * SS + sI) * DD + d;
            uint32_t hi, lo;
            cvt_pair(x, y, hi, lo);
            *(uint32_t*)(Ch + idx) = hi;
            *(uint32_t*)(Cl + idx) = lo;
        } else if (MODE == 2) {
            int h = n >> 6, d = n & 63, b = m >> 10, sI = m & 1023;
            long base = ((long)(b * HH + h) * DD + d) * SS + sI;
            __nv_bfloat16 xh = __float2bfloat16(x);
            __nv_bfloat16 xl = __float2bfloat16(x - __bfloat162float(xh));
            __nv_bfloat16 yh = __float2bfloat16(y);
            __nv_bfloat16 yl = __float2bfloat16(y - __bfloat162float(yh));
            Ch[base] = xh; Cl[base] = xl;
            Ch[base + SS] = yh; Cl[base + SS] = yl;
        } else {
            int z = blockIdx.z, b = z >> 4, h = z & 15;
            long idx = ((long)(b * SS + m)) * DMM + h * DD + n;
            uint32_t hi, lo;
            cvt_pair(x, y, hi, lo);
            *(uint32_t*)(Ch + idx) = hi;
            *(uint32_t*)(Cl + idx) = lo;
        }
    };

#pragma unroll
    for (int mt = 0; mt < 2; ++mt)
#pragma unroll
        for (int nt = 0; nt < 2 * NTP; ++nt) {
            int m = m0 + wm + mt * 16 + (lane >> 2);
            int n = n0 + wn + nt * 8 + (lane & 3) * 2;
            emit(m,     n, acc[mt][nt][0], acc[mt][nt][1]);
            emit(m + 8, n, acc[mt][nt][2], acc[mt][nt][3]);
        }
}

// ---------------------------------------------------------------------------
// Row softmax in place (1024 per row)
// ---------------------------------------------------------------------------
__global__ void __launch_bounds__(256) softmax_rows(float* __restrict__ attn)
{
    const long row = blockIdx.x;
    float* p = attn + row * 1024;
    const int tid = threadIdx.x;
    float4 v = ((float4*)p)[tid];

    float m = fmaxf(fmaxf(v.x, v.y), fmaxf(v.z, v.w));
#pragma unroll
    for (int o = 16; o; o >>= 1) m = fmaxf(m, __shfl_xor_sync(0xffffffffu, m, o));

    __shared__ float sm[8], ssum[8];
    const int wid = tid >> 5, lid = tid & 31;
    if (lid == 0) sm[wid] = m;
    __syncthreads();
    float bm = sm[0];
#pragma unroll
    for (int i = 1; i < 8; ++i) bm = fmaxf(bm, sm[i]);

    float e0 = __expf(v.x - bm), e1 = __expf(v.y - bm);
    float e2 = __expf(v.z - bm), e3 = __expf(v.w - bm);
    float s = e0 + e1 + e2 + e3;
#pragma unroll
    for (int o = 16; o; o >>= 1) s += __shfl_xor_sync(0xffffffffu, s, o);
    if (lid == 0) ssum[wid] = s;
    __syncthreads();
    float bs = 0.f;
#pragma unroll
    for (int i = 0; i < 8; ++i) bs += ssum[i];

    float inv = 1.0f / bs;
    ((float4*)p)[tid] = make_float4(e0 * inv, e1 * inv, e2 * inv, e3 * inv);
}

// ---------------------------------------------------------------------------
extern "C" void kernel_launch(void* const* d_in, const int* in_sizes, int n_in,
                              void* d_out, int out_size)
{
    const float* query = (const float*)d_in[0];
    const float* key   = (const float*)d_in[1];
    const float* value = (const float*)d_in[2];
    const float* Wq    = (const float*)d_in[3];
    const float* Wk    = (const float*)d_in[4];
    const float* Wv    = (const float*)d_in[5];
    const float* Wo    = (const float*)d_in[6];
    float* out = (float*)d_out;

    __nv_bfloat16 *XQh, *XQl, *XKh, *XKl, *XVh, *XVl;
    __nv_bfloat16 *Wqh, *Wql, *Wkh, *Wkl, *Wvh, *Wvl, *Woh, *Wol;
    __nv_bfloat16 *Qh, *Ql, *Kh, *Kl, *Vth, *Vtl, *Chp, *Clp;
    float* Ap;
    cudaGetSymbolAddress((void**)&XQh, g_XQh); cudaGetSymbolAddress((void**)&XQl, g_XQl);
    cudaGetSymbolAddress((void**)&XKh, g_XKh); cudaGetSymbolAddress((void**)&XKl, g_XKl);
    cudaGetSymbolAddress((void**)&XVh, g_XVh); cudaGetSymbolAddress((void**)&XVl, g_XVl);
    cudaGetSymbolAddress((void**)&Wqh, g_Wqh); cudaGetSymbolAddress((void**)&Wql, g_Wql);
    cudaGetSymbolAddress((void**)&Wkh, g_Wkh); cudaGetSymbolAddress((void**)&Wkl, g_Wkl);
    cudaGetSymbolAddress((void**)&Wvh, g_Wvh); cudaGetSymbolAddress((void**)&Wvl, g_Wvl);
    cudaGetSymbolAddress((void**)&Woh, g_Woh); cudaGetSymbolAddress((void**)&Wol, g_Wol);
    cudaGetSymbolAddress((void**)&Qh, g_Qh);   cudaGetSymbolAddress((void**)&Ql, g_Ql);
    cudaGetSymbolAddress((void**)&Kh, g_Kh);   cudaGetSymbolAddress((void**)&Kl, g_Kl);
    cudaGetSymbolAddress((void**)&Vth, g_Vth); cudaGetSymbolAddress((void**)&Vtl, g_Vtl);
    cudaGetSymbolAddress((void**)&Chp, g_Ch);  cudaGetSymbolAddress((void**)&Clp, g_Cl);
    cudaGetSymbolAddress((void**)&Ap, g_attn);

    float* attn = ((size_t)out_size >= OUT_ELEMS + ATT_ELEMS) ? (out + OUT_ELEMS) : Ap;

    const int SM128 = 2 * (2 * 128 * 80 + 2 * 128 * 80);  // 81920
    const int SM64  = 2 * (2 * 128 * 80 + 2 * 64 * 80);   // 61440
    cudaFuncSetAttribute(gemm_pp<128, 1, true>, cudaFuncAttributeMaxDynamicSharedMemorySize, SM128);
    cudaFuncSetAttribute(gemm_pp<128, 2, true>, cudaFuncAttributeMaxDynamicSharedMemorySize, SM128);
    cudaFuncSetAttribute(gemm_pp<128, 0, true>, cudaFuncAttributeMaxDynamicSharedMemorySize, SM128);
    cudaFuncSetAttribute(gemm_pp<64, 3, false>, cudaFuncAttributeMaxDynamicSharedMemorySize, SM64);

    // 1) split all fp32 inputs to bf16 hi/lo
    split_all<<<16384, 256>>>(query, key, value, Wq, Wk, Wv, Wo);

    dim3 blk(512);

    // 2) projections
    gemm_pp<128, 1, true><<<dim3(8, 32, 1), blk, SM128>>>(
        XQh, XQl, nullptr, Wqh, Wql, nullptr, Qh, Ql,
        DMM, DMM, DMM, 0, 0, 0, 0, 1.0f);
    gemm_pp<128, 1, true><<<dim3(8, 32, 1), blk, SM128>>>(
        XKh, XKl, nullptr, Wkh, Wkl, nullptr, Kh, Kl,
        DMM, DMM, DMM, 0, 0, 0, 0, 1.0f);
    gemm_pp<128, 2, true><<<dim3(8, 32, 1), blk, SM128>>>(
        XVh, XVl, nullptr, Wvh, Wvl, nullptr, Vth, Vtl,
        DMM, DMM, DMM, 0, 0, 0, 0, 1.0f);

    // 3) scores = (Q K^T)/8
    gemm_pp<128, 0, true><<<dim3(8, 8, BB * HH), blk, SM128>>>(
        Qh, Ql, nullptr, Kh, Kl, attn, nullptr, nullptr,
        DD, DD, DD, SS, (long)SS * DD, (long)SS * DD, (long)SS * SS, 0.125f);

    // 4) softmax in place
    softmax_rows<<<BB * HH * SS, 256>>>(attn);

    // 5) ctx = attn @ V
    gemm_pp<64, 3, false><<<dim3(1, 8, BB * HH), blk, SM64>>>(
        nullptr, nullptr, attn, Vth, Vtl, nullptr, Chp, Clp,
        SS, SS, SS, 0, (long)SS * SS, (long)DD * SS, 0, 1.0f);

    // 6) out = ctx @ Wo^T
    gemm_pp<128, 0, true><<<dim3(8, 32, 1), blk, SM128>>>(
        Chp, Clp, nullptr, Woh, Wol, out, nullptr, nullptr,
        DMM, DMM, DMM, DMM, 0, 0, 0, 1.0f);
}